// round 1
// baseline (speedup 1.0000x reference)
#include <cuda_runtime.h>
#include <math.h>

// ---------------- problem constants ----------------
#define TOK    2048          // B*T
#define DMODEL 1024
#define DQKV   3072
#define DFF    4096
#define NL     8

// ---------------- scratch (device globals, no allocs) ----------------
__device__ float g_x   [TOK * DMODEL];
__device__ float g_qkv [TOK * DQKV];
__device__ float g_attn[TOK * DMODEL];
__device__ float g_ln  [TOK * DMODEL];
__device__ float g_ff  [TOK * DFF];
__device__ float g_xc  [TOK * 2 * DMODEL];
__device__ float g_sv2 [TOK * DMODEL];
__device__ float g_sv3 [TOK * DMODEL];
__device__ float g_sv4 [TOK * DMODEL];

// ---------------- SGEMM: C = act(A * W^T + bias) + res ----------------
// A: [M,K] row-major, W: [N,K] row-major. FLAGS bit0=bias, bit1=gelu, bit2=residual.
#define BM 128
#define BN 128
#define BK 8

template<int FLAGS>
__global__ void __launch_bounds__(256) sgemm_kernel(
    const float* __restrict__ A, const float* __restrict__ W,
    const float* __restrict__ bias, const float* __restrict__ res,
    float* __restrict__ C, int M, int N, int K)
{
    __shared__ float As[BK][BM];
    __shared__ float Bs[BK][BN];
    const int tid = threadIdx.x;
    const int bm = blockIdx.y * BM;
    const int bn = blockIdx.x * BN;
    const int tx = tid & 15;
    const int ty = tid >> 4;
    const int lr = tid >> 1;        // 0..127
    const int lc = (tid & 1) * 4;   // 0 or 4

    const float* Ag = A + (size_t)(bm + lr) * K + lc;
    const float* Wg = W + (size_t)(bn + lr) * K + lc;

    float acc[8][8];
#pragma unroll
    for (int i = 0; i < 8; i++)
#pragma unroll
        for (int j = 0; j < 8; j++) acc[i][j] = 0.f;

    for (int k0 = 0; k0 < K; k0 += BK) {
        float4 av = *(const float4*)(Ag + k0);
        float4 bv = *(const float4*)(Wg + k0);
        __syncthreads();
        As[lc + 0][lr] = av.x; As[lc + 1][lr] = av.y;
        As[lc + 2][lr] = av.z; As[lc + 3][lr] = av.w;
        Bs[lc + 0][lr] = bv.x; Bs[lc + 1][lr] = bv.y;
        Bs[lc + 2][lr] = bv.z; Bs[lc + 3][lr] = bv.w;
        __syncthreads();
#pragma unroll
        for (int k = 0; k < BK; k++) {
            float a[8], b[8];
            *(float4*)(a)     = *(const float4*)&As[k][ty * 4];
            *(float4*)(a + 4) = *(const float4*)&As[k][64 + ty * 4];
            *(float4*)(b)     = *(const float4*)&Bs[k][tx * 4];
            *(float4*)(b + 4) = *(const float4*)&Bs[k][64 + tx * 4];
#pragma unroll
            for (int i = 0; i < 8; i++)
#pragma unroll
                for (int j = 0; j < 8; j++)
                    acc[i][j] = fmaf(a[i], b[j], acc[i][j]);
        }
    }

#pragma unroll
    for (int i = 0; i < 8; i++) {
        const int row = bm + ((i < 4) ? (ty * 4 + i) : (64 + ty * 4 + (i - 4)));
#pragma unroll
        for (int jh = 0; jh < 2; jh++) {
            const int col = bn + ((jh == 0) ? (tx * 4) : (64 + tx * 4));
            float v0 = acc[i][jh * 4 + 0];
            float v1 = acc[i][jh * 4 + 1];
            float v2 = acc[i][jh * 4 + 2];
            float v3 = acc[i][jh * 4 + 3];
            if (FLAGS & 1) {
                v0 += bias[col + 0]; v1 += bias[col + 1];
                v2 += bias[col + 2]; v3 += bias[col + 3];
            }
            if (FLAGS & 2) {
                v0 = 0.5f * v0 * (1.f + erff(v0 * 0.7071067811865476f));
                v1 = 0.5f * v1 * (1.f + erff(v1 * 0.7071067811865476f));
                v2 = 0.5f * v2 * (1.f + erff(v2 * 0.7071067811865476f));
                v3 = 0.5f * v3 * (1.f + erff(v3 * 0.7071067811865476f));
            }
            if (FLAGS & 4) {
                float4 r4 = *(const float4*)(res + (size_t)row * N + col);
                v0 += r4.x; v1 += r4.y; v2 += r4.z; v3 += r4.w;
            }
            float4 o4; o4.x = v0; o4.y = v1; o4.z = v2; o4.w = v3;
            *(float4*)(C + (size_t)row * N + col) = o4;
        }
    }
}

// ---------------- attention: non-causal softmax(QK^T/8 + alibi) V -------------
// grid (T/64, H, B), 256 threads. 64x64 flash tiles, online softmax.
#define APAD 68   // row stride (floats), 16B-aligned, conflict-mitigating

__global__ void __launch_bounds__(256) attn_kernel(
    const float* __restrict__ qkv, float* __restrict__ out)
{
    extern __shared__ float sm[];
    float* Qs = sm;                  // [64][APAD]
    float* Ks = sm + 64 * APAD;      // reused as Ps
    float* Vs = sm + 2 * 64 * APAD;

    const int b  = blockIdx.z;
    const int h  = blockIdx.y;
    const int q0 = blockIdx.x * 64;
    const int tid = threadIdx.x;
    const int tx = tid & 15;
    const int ty = tid >> 4;
    const float slope = -exp2f(-0.5f * (float)(h + 1));
    const size_t base = (size_t)b * 1024 * DQKV + (size_t)h * 64;

    // load Q tile, pre-scaled by 1/sqrt(DH)=0.125
    {
        const int r = tid >> 2;
        const int c = (tid & 3) * 16;
        const float* src = qkv + base + (size_t)(q0 + r) * DQKV + c;
        float* dst = Qs + r * APAD + c;
#pragma unroll
        for (int u = 0; u < 4; u++) {
            float4 v4 = *(const float4*)(src + u * 4);
            dst[u * 4 + 0] = v4.x * 0.125f; dst[u * 4 + 1] = v4.y * 0.125f;
            dst[u * 4 + 2] = v4.z * 0.125f; dst[u * 4 + 3] = v4.w * 0.125f;
        }
    }

    float m_r[4], l_r[4], o_acc[4][4];
#pragma unroll
    for (int i = 0; i < 4; i++) {
        m_r[i] = -1e30f; l_r[i] = 0.f;
#pragma unroll
        for (int j = 0; j < 4; j++) o_acc[i][j] = 0.f;
    }

    for (int kt = 0; kt < 16; kt++) {
        const int k0 = kt * 64;
        __syncthreads();                         // prev PV done; safe to refill K/V
        {
            const int r = tid >> 2;
            const int c = (tid & 3) * 16;
            const float* ks = qkv + base + 1024 + (size_t)(k0 + r) * DQKV + c;
            const float* vs = qkv + base + 2048 + (size_t)(k0 + r) * DQKV + c;
#pragma unroll
            for (int u = 0; u < 4; u++) {
                *(float4*)(Ks + r * APAD + c + u * 4) = *(const float4*)(ks + u * 4);
                *(float4*)(Vs + r * APAD + c + u * 4) = *(const float4*)(vs + u * 4);
            }
        }
        __syncthreads();

        // scores: thread owns rows ty*4+i, cols tx + 16*j (conflict-free K reads)
        float s[4][4];
#pragma unroll
        for (int i = 0; i < 4; i++)
#pragma unroll
            for (int j = 0; j < 4; j++) s[i][j] = 0.f;

        for (int d = 0; d < 64; d += 4) {
            float4 qv[4], kv[4];
#pragma unroll
            for (int i = 0; i < 4; i++)
                qv[i] = *(const float4*)(Qs + (ty * 4 + i) * APAD + d);
#pragma unroll
            for (int j = 0; j < 4; j++)
                kv[j] = *(const float4*)(Ks + (tx + j * 16) * APAD + d);
#pragma unroll
            for (int i = 0; i < 4; i++)
#pragma unroll
                for (int j = 0; j < 4; j++) {
                    s[i][j] = fmaf(qv[i].x, kv[j].x, s[i][j]);
                    s[i][j] = fmaf(qv[i].y, kv[j].y, s[i][j]);
                    s[i][j] = fmaf(qv[i].z, kv[j].z, s[i][j]);
                    s[i][j] = fmaf(qv[i].w, kv[j].w, s[i][j]);
                }
        }

        // alibi + tile row max
        float tmax[4] = {-1e30f, -1e30f, -1e30f, -1e30f};
#pragma unroll
        for (int i = 0; i < 4; i++) {
            const int qi = q0 + ty * 4 + i;
#pragma unroll
            for (int j = 0; j < 4; j++) {
                const int kj = k0 + tx + j * 16;
                const float bias = (qi < 1023 && kj < 1023)
                                 ? slope * fabsf((float)(qi - kj)) : 0.f;
                s[i][j] += bias;
                tmax[i] = fmaxf(tmax[i], s[i][j]);
            }
        }
#pragma unroll
        for (int off = 8; off; off >>= 1)
#pragma unroll
            for (int i = 0; i < 4; i++)
                tmax[i] = fmaxf(tmax[i], __shfl_xor_sync(0xffffffffu, tmax[i], off));

        float alpha[4], rsum[4];
#pragma unroll
        for (int i = 0; i < 4; i++) {
            const float nm = fmaxf(m_r[i], tmax[i]);
            alpha[i] = expf(m_r[i] - nm);
            m_r[i] = nm;
            rsum[i] = 0.f;
        }
#pragma unroll
        for (int i = 0; i < 4; i++)
#pragma unroll
            for (int j = 0; j < 4; j++) {
                const float p = expf(s[i][j] - m_r[i]);
                s[i][j] = p;
                rsum[i] += p;
            }
#pragma unroll
        for (int off = 8; off; off >>= 1)
#pragma unroll
            for (int i = 0; i < 4; i++)
                rsum[i] += __shfl_xor_sync(0xffffffffu, rsum[i], off);
#pragma unroll
        for (int i = 0; i < 4; i++) {
            l_r[i] = l_r[i] * alpha[i] + rsum[i];
#pragma unroll
            for (int j = 0; j < 4; j++) o_acc[i][j] *= alpha[i];
        }

        __syncthreads();                         // all K reads done; reuse as P
        float* Ps = Ks;
#pragma unroll
        for (int i = 0; i < 4; i++)
#pragma unroll
            for (int j = 0; j < 4; j++)
                Ps[(ty * 4 + i) * APAD + tx + j * 16] = s[i][j];
        __syncthreads();

        // O += P * V : thread accumulates rows ty*4+i, dims tx*4..tx*4+3
        for (int j = 0; j < 64; j++) {
            const float4 vv = *(const float4*)(Vs + j * APAD + tx * 4);
#pragma unroll
            for (int i = 0; i < 4; i++) {
                const float p = Ps[(ty * 4 + i) * APAD + j];
                o_acc[i][0] = fmaf(p, vv.x, o_acc[i][0]);
                o_acc[i][1] = fmaf(p, vv.y, o_acc[i][1]);
                o_acc[i][2] = fmaf(p, vv.z, o_acc[i][2]);
                o_acc[i][3] = fmaf(p, vv.w, o_acc[i][3]);
            }
        }
    }

#pragma unroll
    for (int i = 0; i < 4; i++) {
        const float inv = 1.f / l_r[i];
        const int qi = q0 + ty * 4 + i;
        float4 v;
        v.x = o_acc[i][0] * inv; v.y = o_acc[i][1] * inv;
        v.z = o_acc[i][2] * inv; v.w = o_acc[i][3] * inv;
        *(float4*)(out + ((size_t)b * 1024 + qi) * DMODEL + h * 64 + tx * 4) = v;
    }
}

// ---------------- LayerNorm (two-pass, matches reference) ----------------
__global__ void __launch_bounds__(256) ln_kernel(
    const float* __restrict__ x, const float* __restrict__ g,
    float* __restrict__ y)
{
    __shared__ float red[256];
    const int row = blockIdx.x;
    const int tid = threadIdx.x;
    const float* xr = x + (size_t)row * DMODEL;

    float v[4];
    float s = 0.f;
#pragma unroll
    for (int u = 0; u < 4; u++) { v[u] = xr[tid + u * 256]; s += v[u]; }
    red[tid] = s; __syncthreads();
    for (int o = 128; o; o >>= 1) {
        if (tid < o) red[tid] += red[tid + o];
        __syncthreads();
    }
    const float mu = red[0] * (1.f / 1024.f);
    __syncthreads();

    float q = 0.f;
#pragma unroll
    for (int u = 0; u < 4; u++) { const float d = v[u] - mu; q += d * d; }
    red[tid] = q; __syncthreads();
    for (int o = 128; o; o >>= 1) {
        if (tid < o) red[tid] += red[tid + o];
        __syncthreads();
    }
    const float r = rsqrtf(red[0] * (1.f / 1024.f) + 1e-5f);

#pragma unroll
    for (int u = 0; u < 4; u++)
        y[(size_t)row * DMODEL + tid + u * 256] = (v[u] - mu) * r * g[tid + u * 256];
}

// ---------------- skip concat: xc = [x, s * 2^-0.5] ----------------
__global__ void __launch_bounds__(256) concat_kernel(
    const float* __restrict__ x, const float* __restrict__ s,
    float* __restrict__ xc)
{
    const int idx = blockIdx.x * blockDim.x + threadIdx.x;
    const int row = idx >> 10;
    const int col = idx & 1023;
    float* dst = xc + (size_t)row * (2 * DMODEL);
    dst[col] = x[idx];
    dst[DMODEL + col] = s[idx] * 0.70710678118654752440f;
}

// ---------------- host orchestration ----------------
extern "C" void kernel_launch(void* const* d_in, const int* in_sizes, int n_in,
                              void* d_out, int out_size)
{
    (void)in_sizes; (void)n_in; (void)out_size;
    const float* x_in       = (const float*)d_in[0];
    const float* attn_w     = (const float*)d_in[1];
    const float* attn_out_w = (const float*)d_in[2];
    const float* mlp_ln_g   = (const float*)d_in[3];
    const float* mlp_in_w   = (const float*)d_in[4];
    const float* mlp_in_b   = (const float*)d_in[5];
    const float* mlp_out_w  = (const float*)d_in[6];
    const float* mlp_out_b  = (const float*)d_in[7];
    const float* skip_w     = (const float*)d_in[8];
    const float* skip_b     = (const float*)d_in[9];
    const float* out_ln_g   = (const float*)d_in[10];

    float *gx, *gqkv, *gattn, *gln, *gff, *gxc, *gs2, *gs3, *gs4;
    cudaGetSymbolAddress((void**)&gx,    g_x);
    cudaGetSymbolAddress((void**)&gqkv,  g_qkv);
    cudaGetSymbolAddress((void**)&gattn, g_attn);
    cudaGetSymbolAddress((void**)&gln,   g_ln);
    cudaGetSymbolAddress((void**)&gff,   g_ff);
    cudaGetSymbolAddress((void**)&gxc,   g_xc);
    cudaGetSymbolAddress((void**)&gs2,   g_sv2);
    cudaGetSymbolAddress((void**)&gs3,   g_sv3);
    cudaGetSymbolAddress((void**)&gs4,   g_sv4);

    const int ATTN_SMEM = 3 * 64 * APAD * (int)sizeof(float);
    cudaFuncSetAttribute(attn_kernel,
                         cudaFuncAttributeMaxDynamicSharedMemorySize, ATTN_SMEM);

    const size_t XBYTES = sizeof(float) * (size_t)TOK * DMODEL;
    cudaMemcpyAsync(gx, x_in, XBYTES, cudaMemcpyDeviceToDevice, 0);

    for (int i = 0; i < NL; i++) {
        if (i >= 5) {
            // pop order: layer5 <- save after block4, layer6 <- block3, layer7 <- block2
            float* sv = (i == 5) ? gs4 : (i == 6) ? gs3 : gs2;
            concat_kernel<<<(TOK * DMODEL) / 256, 256>>>(gx, sv, gxc);
            const int j = i - 4;
            sgemm_kernel<1><<<dim3(DMODEL / BN, TOK / BM), 256>>>(
                gxc, skip_w + (size_t)j * DMODEL * 2 * DMODEL,
                skip_b + (size_t)j * DMODEL, nullptr, gx,
                TOK, DMODEL, 2 * DMODEL);
        }
        // QKV projection
        sgemm_kernel<0><<<dim3(DQKV / BN, TOK / BM), 256>>>(
            gx, attn_w + (size_t)i * DQKV * DMODEL, nullptr, nullptr, gqkv,
            TOK, DQKV, DMODEL);
        // attention
        attn_kernel<<<dim3(16, 16, 2), 256, ATTN_SMEM>>>(gqkv, gattn);
        // output projection + residual
        sgemm_kernel<4><<<dim3(DMODEL / BN, TOK / BM), 256>>>(
            gattn, attn_out_w + (size_t)i * DMODEL * DMODEL, nullptr, gx, gx,
            TOK, DMODEL, DMODEL);
        // MLP LN
        ln_kernel<<<TOK, 256>>>(gx, mlp_ln_g + (size_t)i * DMODEL, gln);
        // MLP in + bias + exact GELU
        sgemm_kernel<3><<<dim3(DFF / BN, TOK / BM), 256>>>(
            gln, mlp_in_w + (size_t)i * DFF * DMODEL,
            mlp_in_b + (size_t)i * DFF, nullptr, gff,
            TOK, DFF, DMODEL);
        // MLP out + bias + residual
        sgemm_kernel<5><<<dim3(DMODEL / BN, TOK / BM), 256>>>(
            gff, mlp_out_w + (size_t)i * DMODEL * DFF,
            mlp_out_b + (size_t)i * DMODEL, gx, gx,
            TOK, DMODEL, DFF);
        // save connections (appended for i<=4; only 2,3,4 are ever popped)
        if (i == 2) cudaMemcpyAsync(gs2, gx, XBYTES, cudaMemcpyDeviceToDevice, 0);
        if (i == 3) cudaMemcpyAsync(gs3, gx, XBYTES, cudaMemcpyDeviceToDevice, 0);
        if (i == 4) cudaMemcpyAsync(gs4, gx, XBYTES, cudaMemcpyDeviceToDevice, 0);
    }

    // final LN into d_out
    ln_kernel<<<TOK, 256>>>(gx, out_ln_g, (float*)d_out);
}

// round 4
// speedup vs baseline: 2.0080x; 2.0080x over previous
#include <cuda_runtime.h>
#include <cuda_bf16.h>
#include <math.h>
#include <stdint.h>

// ---------------- problem constants ----------------
#define TOK    2048
#define DMODEL 1024
#define DQKV   3072
#define DFF    4096
#define NL     8

// ---------------- scratch (device globals, no allocs) ----------------
__device__ float g_x   [TOK * DMODEL];
__device__ float g_qkv [TOK * DQKV];
__device__ float g_sv2 [TOK * DMODEL];
__device__ float g_sv3 [TOK * DMODEL];
__device__ float g_sv4 [TOK * DMODEL];

// activation hi/lo pairs
__device__ __nv_bfloat16 a_x_h   [TOK * DMODEL];
__device__ __nv_bfloat16 a_x_l   [TOK * DMODEL];
__device__ __nv_bfloat16 a_at_h  [TOK * DMODEL];
__device__ __nv_bfloat16 a_at_l  [TOK * DMODEL];
__device__ __nv_bfloat16 a_ln_h  [TOK * DMODEL];
__device__ __nv_bfloat16 a_ln_l  [TOK * DMODEL];
__device__ __nv_bfloat16 a_ff_h  [TOK * DFF];
__device__ __nv_bfloat16 a_ff_l  [TOK * DFF];
__device__ __nv_bfloat16 a_xc_h  [TOK * 2 * DMODEL];
__device__ __nv_bfloat16 a_xc_l  [TOK * 2 * DMODEL];

// weight hi/lo pairs
__device__ __nv_bfloat16 w_qkv_h[NL * DQKV * DMODEL];
__device__ __nv_bfloat16 w_qkv_l[NL * DQKV * DMODEL];
__device__ __nv_bfloat16 w_ao_h [NL * DMODEL * DMODEL];
__device__ __nv_bfloat16 w_ao_l [NL * DMODEL * DMODEL];
__device__ __nv_bfloat16 w_mi_h [NL * DFF * DMODEL];
__device__ __nv_bfloat16 w_mi_l [NL * DFF * DMODEL];
__device__ __nv_bfloat16 w_mo_h [NL * DMODEL * DFF];
__device__ __nv_bfloat16 w_mo_l [NL * DMODEL * DFF];
__device__ __nv_bfloat16 w_sk_h [4 * DMODEL * 2 * DMODEL];
__device__ __nv_bfloat16 w_sk_l [4 * DMODEL * 2 * DMODEL];

// ---------------- helpers ----------------
__device__ __forceinline__ uint32_t smem_u32(const void* p) {
    uint32_t a;
    asm("{ .reg .u64 t; cvta.to.shared.u64 t, %1; cvt.u32.u64 %0, t; }"
        : "=r"(a) : "l"(p));
    return a;
}

__device__ __forceinline__ void cp16(uint32_t dst, const void* src) {
    asm volatile("cp.async.cg.shared.global [%0], [%1], 16;" :: "r"(dst), "l"(src));
}

__device__ __forceinline__ void ldm_x4(uint32_t addr, uint32_t& r0, uint32_t& r1,
                                       uint32_t& r2, uint32_t& r3) {
    asm volatile("ldmatrix.sync.aligned.m8n8.x4.shared.b16 {%0,%1,%2,%3}, [%4];"
                 : "=r"(r0), "=r"(r1), "=r"(r2), "=r"(r3) : "r"(addr));
}

__device__ __forceinline__ void mma16816(float* c, const uint32_t* a,
                                         uint32_t b0, uint32_t b1) {
    asm volatile(
        "mma.sync.aligned.m16n8k16.row.col.f32.bf16.bf16.f32 "
        "{%0,%1,%2,%3}, {%4,%5,%6,%7}, {%8,%9}, {%0,%1,%2,%3};"
        : "+f"(c[0]), "+f"(c[1]), "+f"(c[2]), "+f"(c[3])
        : "r"(a[0]), "r"(a[1]), "r"(a[2]), "r"(a[3]), "r"(b0), "r"(b1));
}

__device__ __forceinline__ void split2(float v, uint16_t& h, uint16_t& l) {
    __nv_bfloat16 hb = __float2bfloat16_rn(v);
    __nv_bfloat16 lb = __float2bfloat16_rn(v - __bfloat162float(hb));
    h = *(uint16_t*)&hb;
    l = *(uint16_t*)&lb;
}

// ---------------- bf16x3 HMMA GEMM: C = act(A * W^T + bias) (+res) ----------------
// A = Ah+Al [M,K], W = Wh+Wl [N,K], both row-major bf16 pairs.
// acc = Ah*Wh + Al*Wh + Ah*Wl  (fp32 accum; lo*lo dropped ~2^-16)
// FLAGS: 1=bias, 2=gelu, 4=residual(fp32), 8=write bf16 hi/lo, 16=write fp32
#define GBK     32
#define GROWB   80                       // smem row stride (bytes), conflict-free
#define GTILEB  (128 * GROWB)            // 10240 B per 128x32 bf16 tile
#define GSTRIDE (4 * GTILEB)             // Ah|Al|Wh|Wl per stage = 40960 B
#define GNST    4
#define GEMM_SMEM (GNST * GSTRIDE)       // 163840 B

template<int FLAGS>
__global__ void __launch_bounds__(256) gemm_hmma3(
    const __nv_bfloat16* __restrict__ Ah, const __nv_bfloat16* __restrict__ Al,
    const __nv_bfloat16* __restrict__ Wh, const __nv_bfloat16* __restrict__ Wl,
    const float* __restrict__ bias, const float* __restrict__ res,
    float* __restrict__ C, __nv_bfloat16* __restrict__ Cbh,
    __nv_bfloat16* __restrict__ Cbl, int N, int K)
{
    extern __shared__ char smem[];
    const uint32_t sb = smem_u32(smem);
    const int tid  = threadIdx.x;
    const int wid  = tid >> 5;
    const int lane = tid & 31;
    const int wm   = wid >> 2;
    const int wn   = wid & 3;
    const int bm   = blockIdx.y * 128;
    const int bn   = blockIdx.x * 128;

    const int ldrow = tid >> 1;
    const int ldc   = (tid & 1) * 2;
    const size_t arow = (size_t)(bm + ldrow) * K + ldc * 8;
    const size_t wrow = (size_t)(bn + ldrow) * K + ldc * 8;
    const uint32_t sArow = ldrow * GROWB + ldc * 16;

    auto load_stage = [&](int s) {
        const uint32_t base = sb + (s & (GNST - 1)) * GSTRIDE;
        const size_t ko = (size_t)s * GBK;
        cp16(base + sArow,                    Ah + arow + ko);
        cp16(base + sArow + 16,               Ah + arow + ko + 8);
        cp16(base + GTILEB + sArow,           Al + arow + ko);
        cp16(base + GTILEB + sArow + 16,      Al + arow + ko + 8);
        cp16(base + 2 * GTILEB + sArow,       Wh + wrow + ko);
        cp16(base + 2 * GTILEB + sArow + 16,  Wh + wrow + ko + 8);
        cp16(base + 3 * GTILEB + sArow,       Wl + wrow + ko);
        cp16(base + 3 * GTILEB + sArow + 16,  Wl + wrow + ko + 8);
        asm volatile("cp.async.commit_group;");
    };

    const int S = K / GBK;
    for (int s = 0; s < GNST - 1; s++) load_stage(s);

    float acc[4][4][4];
#pragma unroll
    for (int i = 0; i < 4; i++)
#pragma unroll
        for (int j = 0; j < 4; j++)
#pragma unroll
            for (int k = 0; k < 4; k++) acc[i][j][k] = 0.f;

    const uint32_t aoff = (uint32_t)(wm * 64 + (lane & 15)) * GROWB + (lane >> 4) * 16;
    const uint32_t boff = (uint32_t)(wn * 32 + (lane & 7) + ((lane >> 4) & 1) * 8) * GROWB
                        + ((lane >> 3) & 1) * 16;

    for (int s = 0; s < S; s++) {
        asm volatile("cp.async.wait_group 2;" ::: "memory");
        __syncthreads();

        const int pf = s + GNST - 1;
        if (pf < S) load_stage(pf);
        else        asm volatile("cp.async.commit_group;");

        const uint32_t base = sb + (s & (GNST - 1)) * GSTRIDE;
#pragma unroll
        for (int k16 = 0; k16 < 2; k16++) {
            uint32_t ah[4][4], al[4][4], bh[2][4], bl[2][4];
#pragma unroll
            for (int fm = 0; fm < 4; fm++) {
                const uint32_t ao = aoff + fm * 16 * GROWB + k16 * 32;
                ldm_x4(base + ao,          ah[fm][0], ah[fm][1], ah[fm][2], ah[fm][3]);
                ldm_x4(base + GTILEB + ao, al[fm][0], al[fm][1], al[fm][2], al[fm][3]);
            }
#pragma unroll
            for (int fnp = 0; fnp < 2; fnp++) {
                const uint32_t bo = boff + fnp * 16 * GROWB + k16 * 32;
                ldm_x4(base + 2 * GTILEB + bo, bh[fnp][0], bh[fnp][1], bh[fnp][2], bh[fnp][3]);
                ldm_x4(base + 3 * GTILEB + bo, bl[fnp][0], bl[fnp][1], bl[fnp][2], bl[fnp][3]);
            }
#pragma unroll
            for (int fm = 0; fm < 4; fm++) {
#pragma unroll
                for (int fnp = 0; fnp < 2; fnp++) {
                    float* c0 = acc[fm][fnp * 2 + 0];
                    float* c1 = acc[fm][fnp * 2 + 1];
                    mma16816(c0, ah[fm], bh[fnp][0], bh[fnp][1]);
                    mma16816(c0, al[fm], bh[fnp][0], bh[fnp][1]);
                    mma16816(c0, ah[fm], bl[fnp][0], bl[fnp][1]);
                    mma16816(c1, ah[fm], bh[fnp][2], bh[fnp][3]);
                    mma16816(c1, al[fm], bh[fnp][2], bh[fnp][3]);
                    mma16816(c1, ah[fm], bl[fnp][2], bl[fnp][3]);
                }
            }
        }
    }

    // ---- epilogue ----
#pragma unroll
    for (int fm = 0; fm < 4; fm++) {
#pragma unroll
        for (int fn = 0; fn < 4; fn++) {
            const int r0 = bm + wm * 64 + fm * 16 + (lane >> 2);
            const int c0 = bn + wn * 32 + fn * 8 + (lane & 3) * 2;
            float v[4] = { acc[fm][fn][0], acc[fm][fn][1],
                           acc[fm][fn][2], acc[fm][fn][3] };
            if (FLAGS & 1) {
                const float b0 = __ldg(bias + c0), b1 = __ldg(bias + c0 + 1);
                v[0] += b0; v[1] += b1; v[2] += b0; v[3] += b1;
            }
            if (FLAGS & 2) {
#pragma unroll
                for (int u = 0; u < 4; u++)
                    v[u] = 0.5f * v[u] * (1.f + erff(v[u] * 0.7071067811865476f));
            }
            if (FLAGS & 4) {
                const float2 ra = *(const float2*)(res + (size_t)r0 * N + c0);
                const float2 rb = *(const float2*)(res + (size_t)(r0 + 8) * N + c0);
                v[0] += ra.x; v[1] += ra.y; v[2] += rb.x; v[3] += rb.y;
            }
            if (FLAGS & 16) {
                float2 oa; oa.x = v[0]; oa.y = v[1];
                float2 ob; ob.x = v[2]; ob.y = v[3];
                *(float2*)(C + (size_t)r0 * N + c0) = oa;
                *(float2*)(C + (size_t)(r0 + 8) * N + c0) = ob;
            }
            if (FLAGS & 8) {
                uint16_t h0, l0, h1, l1;
                split2(v[0], h0, l0); split2(v[1], h1, l1);
                uint32_t ph = (uint32_t)h0 | ((uint32_t)h1 << 16);
                uint32_t pl = (uint32_t)l0 | ((uint32_t)l1 << 16);
                *(uint32_t*)(Cbh + (size_t)r0 * N + c0) = ph;
                *(uint32_t*)(Cbl + (size_t)r0 * N + c0) = pl;
                split2(v[2], h0, l0); split2(v[3], h1, l1);
                ph = (uint32_t)h0 | ((uint32_t)h1 << 16);
                pl = (uint32_t)l0 | ((uint32_t)l1 << 16);
                *(uint32_t*)(Cbh + (size_t)(r0 + 8) * N + c0) = ph;
                *(uint32_t*)(Cbl + (size_t)(r0 + 8) * N + c0) = pl;
            }
        }
    }
}

// ---------------- attention (fp32 compute, hi/lo bf16 out) ----------------
#define APAD 68

__global__ void __launch_bounds__(256) attn_kernel(
    const float* __restrict__ qkv,
    __nv_bfloat16* __restrict__ out_h, __nv_bfloat16* __restrict__ out_l)
{
    extern __shared__ float sm[];
    float* Qs = sm;
    float* Ks = sm + 64 * APAD;
    float* Vs = sm + 2 * 64 * APAD;

    const int b  = blockIdx.z;
    const int h  = blockIdx.y;
    const int q0 = blockIdx.x * 64;
    const int tid = threadIdx.x;
    const int tx = tid & 15;
    const int ty = tid >> 4;
    const float slope = -exp2f(-0.5f * (float)(h + 1));
    const size_t base = (size_t)b * 1024 * DQKV + (size_t)h * 64;

    {
        const int r = tid >> 2;
        const int c = (tid & 3) * 16;
        const float* src = qkv + base + (size_t)(q0 + r) * DQKV + c;
        float* dst = Qs + r * APAD + c;
#pragma unroll
        for (int u = 0; u < 4; u++) {
            float4 v4 = *(const float4*)(src + u * 4);
            dst[u*4+0] = v4.x * 0.125f; dst[u*4+1] = v4.y * 0.125f;
            dst[u*4+2] = v4.z * 0.125f; dst[u*4+3] = v4.w * 0.125f;
        }
    }

    float m_r[4], l_r[4], o_acc[4][4];
#pragma unroll
    for (int i = 0; i < 4; i++) {
        m_r[i] = -1e30f; l_r[i] = 0.f;
#pragma unroll
        for (int j = 0; j < 4; j++) o_acc[i][j] = 0.f;
    }

    for (int kt = 0; kt < 16; kt++) {
        const int k0 = kt * 64;
        __syncthreads();
        {
            const int r = tid >> 2;
            const int c = (tid & 3) * 16;
            const float* ks = qkv + base + 1024 + (size_t)(k0 + r) * DQKV + c;
            const float* vs = qkv + base + 2048 + (size_t)(k0 + r) * DQKV + c;
#pragma unroll
            for (int u = 0; u < 4; u++) {
                *(float4*)(Ks + r * APAD + c + u * 4) = *(const float4*)(ks + u * 4);
                *(float4*)(Vs + r * APAD + c + u * 4) = *(const float4*)(vs + u * 4);
            }
        }
        __syncthreads();

        float s[4][4];
#pragma unroll
        for (int i = 0; i < 4; i++)
#pragma unroll
            for (int j = 0; j < 4; j++) s[i][j] = 0.f;

        for (int d = 0; d < 64; d += 4) {
            float4 qv[4], kv[4];
#pragma unroll
            for (int i = 0; i < 4; i++)
                qv[i] = *(const float4*)(Qs + (ty * 4 + i) * APAD + d);
#pragma unroll
            for (int j = 0; j < 4; j++)
                kv[j] = *(const float4*)(Ks + (tx + j * 16) * APAD + d);
#pragma unroll
            for (int i = 0; i < 4; i++)
#pragma unroll
                for (int j = 0; j < 4; j++) {
                    s[i][j] = fmaf(qv[i].x, kv[j].x, s[i][j]);
                    s[i][j] = fmaf(qv[i].y, kv[j].y, s[i][j]);
                    s[i][j] = fmaf(qv[i].z, kv[j].z, s[i][j]);
                    s[i][j] = fmaf(qv[i].w, kv[j].w, s[i][j]);
                }
        }

        float tmax[4] = {-1e30f, -1e30f, -1e30f, -1e30f};
#pragma unroll
        for (int i = 0; i < 4; i++) {
            const int qi = q0 + ty * 4 + i;
#pragma unroll
            for (int j = 0; j < 4; j++) {
                const int kj = k0 + tx + j * 16;
                const float bias = (qi < 1023 && kj < 1023)
                                 ? slope * fabsf((float)(qi - kj)) : 0.f;
                s[i][j] += bias;
                tmax[i] = fmaxf(tmax[i], s[i][j]);
            }
        }
#pragma unroll
        for (int off = 8; off; off >>= 1)
#pragma unroll
            for (int i = 0; i < 4; i++)
                tmax[i] = fmaxf(tmax[i], __shfl_xor_sync(0xffffffffu, tmax[i], off));

        float alpha[4], rsum[4];
#pragma unroll
        for (int i = 0; i < 4; i++) {
            const float nm = fmaxf(m_r[i], tmax[i]);
            alpha[i] = expf(m_r[i] - nm);
            m_r[i] = nm;
            rsum[i] = 0.f;
        }
#pragma unroll
        for (int i = 0; i < 4; i++)
#pragma unroll
            for (int j = 0; j < 4; j++) {
                const float p = expf(s[i][j] - m_r[i]);
                s[i][j] = p;
                rsum[i] += p;
            }
#pragma unroll
        for (int off = 8; off; off >>= 1)
#pragma unroll
            for (int i = 0; i < 4; i++)
                rsum[i] += __shfl_xor_sync(0xffffffffu, rsum[i], off);
#pragma unroll
        for (int i = 0; i < 4; i++) {
            l_r[i] = l_r[i] * alpha[i] + rsum[i];
#pragma unroll
            for (int j = 0; j < 4; j++) o_acc[i][j] *= alpha[i];
        }

        __syncthreads();
        float* Ps = Ks;
#pragma unroll
        for (int i = 0; i < 4; i++)
#pragma unroll
            for (int j = 0; j < 4; j++)
                Ps[(ty * 4 + i) * APAD + tx + j * 16] = s[i][j];
        __syncthreads();

        for (int j = 0; j < 64; j++) {
            const float4 vv = *(const float4*)(Vs + j * APAD + tx * 4);
#pragma unroll
            for (int i = 0; i < 4; i++) {
                const float p = Ps[(ty * 4 + i) * APAD + j];
                o_acc[i][0] = fmaf(p, vv.x, o_acc[i][0]);
                o_acc[i][1] = fmaf(p, vv.y, o_acc[i][1]);
                o_acc[i][2] = fmaf(p, vv.z, o_acc[i][2]);
                o_acc[i][3] = fmaf(p, vv.w, o_acc[i][3]);
            }
        }
    }

#pragma unroll
    for (int i = 0; i < 4; i++) {
        const float inv = 1.f / l_r[i];
        const int qi = q0 + ty * 4 + i;
        uint16_t h0, l0;
        uint2 uh, ul;
        uint16_t hh[4], ll[4];
#pragma unroll
        for (int u = 0; u < 4; u++) {
            split2(o_acc[i][u] * inv, h0, l0);
            hh[u] = h0; ll[u] = l0;
        }
        uh.x = (uint32_t)hh[0] | ((uint32_t)hh[1] << 16);
        uh.y = (uint32_t)hh[2] | ((uint32_t)hh[3] << 16);
        ul.x = (uint32_t)ll[0] | ((uint32_t)ll[1] << 16);
        ul.y = (uint32_t)ll[2] | ((uint32_t)ll[3] << 16);
        const size_t o = ((size_t)b * 1024 + qi) * DMODEL + h * 64 + tx * 4;
        *(uint2*)(out_h + o) = uh;
        *(uint2*)(out_l + o) = ul;
    }
}

// ---------------- LayerNorm ----------------
template<bool BF>
__global__ void __launch_bounds__(256) ln_kernel2(
    const float* __restrict__ x, const float* __restrict__ g,
    float* __restrict__ y,
    __nv_bfloat16* __restrict__ yh, __nv_bfloat16* __restrict__ yl)
{
    __shared__ float red[256];
    const int row = blockIdx.x;
    const int tid = threadIdx.x;
    const float* xr = x + (size_t)row * DMODEL;

    float v[4];
    float s = 0.f;
#pragma unroll
    for (int u = 0; u < 4; u++) { v[u] = xr[tid + u * 256]; s += v[u]; }
    red[tid] = s; __syncthreads();
    for (int o = 128; o; o >>= 1) {
        if (tid < o) red[tid] += red[tid + o];
        __syncthreads();
    }
    const float mu = red[0] * (1.f / 1024.f);
    __syncthreads();

    float q = 0.f;
#pragma unroll
    for (int u = 0; u < 4; u++) { const float d = v[u] - mu; q += d * d; }
    red[tid] = q; __syncthreads();
    for (int o = 128; o; o >>= 1) {
        if (tid < o) red[tid] += red[tid + o];
        __syncthreads();
    }
    const float r = rsqrtf(red[0] * (1.f / 1024.f) + 1e-5f);

#pragma unroll
    for (int u = 0; u < 4; u++) {
        const float val = (v[u] - mu) * r * g[tid + u * 256];
        const size_t o = (size_t)row * DMODEL + tid + u * 256;
        if (BF) {
            uint16_t h0, l0;
            split2(val, h0, l0);
            *(uint16_t*)(yh + o) = h0;
            *(uint16_t*)(yl + o) = l0;
        } else {
            y[o] = val;
        }
    }
}

// ---------------- skip concat: xc = [x, s * 2^-0.5] (hi/lo) ----------------
__global__ void __launch_bounds__(256) concat_split_kernel(
    const float* __restrict__ x, const float* __restrict__ s,
    __nv_bfloat16* __restrict__ xch, __nv_bfloat16* __restrict__ xcl)
{
    const int idx = blockIdx.x * blockDim.x + threadIdx.x;
    const int row = idx >> 10;
    const int col = idx & 1023;
    const size_t b = (size_t)row * (2 * DMODEL);
    uint16_t h0, l0;
    split2(x[idx], h0, l0);
    *(uint16_t*)(xch + b + col) = h0;
    *(uint16_t*)(xcl + b + col) = l0;
    split2(s[idx] * 0.70710678118654752440f, h0, l0);
    *(uint16_t*)(xch + b + DMODEL + col) = h0;
    *(uint16_t*)(xcl + b + DMODEL + col) = l0;
}

// ---------------- fp32 -> bf16 hi/lo converters ----------------
__global__ void __launch_bounds__(256) f2bf_split_kernel(
    const float4* __restrict__ in, uint2* __restrict__ oh,
    uint2* __restrict__ ol, int n4)
{
    const int i = blockIdx.x * blockDim.x + threadIdx.x;
    if (i < n4) {
        float4 v = in[i];
        uint16_t h[4], l[4];
        split2(v.x, h[0], l[0]); split2(v.y, h[1], l[1]);
        split2(v.z, h[2], l[2]); split2(v.w, h[3], l[3]);
        uint2 uh, ul;
        uh.x = (uint32_t)h[0] | ((uint32_t)h[1] << 16);
        uh.y = (uint32_t)h[2] | ((uint32_t)h[3] << 16);
        ul.x = (uint32_t)l[0] | ((uint32_t)l[1] << 16);
        ul.y = (uint32_t)l[2] | ((uint32_t)l[3] << 16);
        oh[i] = uh; ol[i] = ul;
    }
}

__global__ void __launch_bounds__(256) initx_kernel(
    const float4* __restrict__ in, float4* __restrict__ xf,
    uint2* __restrict__ xh, uint2* __restrict__ xl, int n4)
{
    const int i = blockIdx.x * blockDim.x + threadIdx.x;
    if (i < n4) {
        float4 v = in[i];
        xf[i] = v;
        uint16_t h[4], l[4];
        split2(v.x, h[0], l[0]); split2(v.y, h[1], l[1]);
        split2(v.z, h[2], l[2]); split2(v.w, h[3], l[3]);
        uint2 uh, ul;
        uh.x = (uint32_t)h[0] | ((uint32_t)h[1] << 16);
        uh.y = (uint32_t)h[2] | ((uint32_t)h[3] << 16);
        ul.x = (uint32_t)l[0] | ((uint32_t)l[1] << 16);
        ul.y = (uint32_t)l[2] | ((uint32_t)l[3] << 16);
        xh[i] = uh; xl[i] = ul;
    }
}

// ---------------- host orchestration ----------------
extern "C" void kernel_launch(void* const* d_in, const int* in_sizes, int n_in,
                              void* d_out, int out_size)
{
    (void)in_sizes; (void)n_in; (void)out_size;
    const float* x_in       = (const float*)d_in[0];
    const float* attn_w     = (const float*)d_in[1];
    const float* attn_out_w = (const float*)d_in[2];
    const float* mlp_ln_g   = (const float*)d_in[3];
    const float* mlp_in_w   = (const float*)d_in[4];
    const float* mlp_in_b   = (const float*)d_in[5];
    const float* mlp_out_w  = (const float*)d_in[6];
    const float* mlp_out_b  = (const float*)d_in[7];
    const float* skip_w     = (const float*)d_in[8];
    const float* skip_b     = (const float*)d_in[9];
    const float* out_ln_g   = (const float*)d_in[10];

    float *gx, *gqkv, *gs2, *gs3, *gs4;
    cudaGetSymbolAddress((void**)&gx,   g_x);
    cudaGetSymbolAddress((void**)&gqkv, g_qkv);
    cudaGetSymbolAddress((void**)&gs2,  g_sv2);
    cudaGetSymbolAddress((void**)&gs3,  g_sv3);
    cudaGetSymbolAddress((void**)&gs4,  g_sv4);

    __nv_bfloat16 *xh, *xl, *ath, *atl, *lnh, *lnl, *ffh, *ffl, *xch, *xcl;
    cudaGetSymbolAddress((void**)&xh,  a_x_h);  cudaGetSymbolAddress((void**)&xl,  a_x_l);
    cudaGetSymbolAddress((void**)&ath, a_at_h); cudaGetSymbolAddress((void**)&atl, a_at_l);
    cudaGetSymbolAddress((void**)&lnh, a_ln_h); cudaGetSymbolAddress((void**)&lnl, a_ln_l);
    cudaGetSymbolAddress((void**)&ffh, a_ff_h); cudaGetSymbolAddress((void**)&ffl, a_ff_l);
    cudaGetSymbolAddress((void**)&xch, a_xc_h); cudaGetSymbolAddress((void**)&xcl, a_xc_l);

    __nv_bfloat16 *wqh, *wql, *waoh, *waol, *wmih, *wmil, *wmoh, *wmol, *wskh, *wskl;
    cudaGetSymbolAddress((void**)&wqh,  w_qkv_h); cudaGetSymbolAddress((void**)&wql,  w_qkv_l);
    cudaGetSymbolAddress((void**)&waoh, w_ao_h);  cudaGetSymbolAddress((void**)&waol, w_ao_l);
    cudaGetSymbolAddress((void**)&wmih, w_mi_h);  cudaGetSymbolAddress((void**)&wmil, w_mi_l);
    cudaGetSymbolAddress((void**)&wmoh, w_mo_h);  cudaGetSymbolAddress((void**)&wmol, w_mo_l);
    cudaGetSymbolAddress((void**)&wskh, w_sk_h);  cudaGetSymbolAddress((void**)&wskl, w_sk_l);

    cudaFuncSetAttribute(gemm_hmma3<16>, cudaFuncAttributeMaxDynamicSharedMemorySize, GEMM_SMEM);
    cudaFuncSetAttribute(gemm_hmma3<28>, cudaFuncAttributeMaxDynamicSharedMemorySize, GEMM_SMEM);
    cudaFuncSetAttribute(gemm_hmma3<11>, cudaFuncAttributeMaxDynamicSharedMemorySize, GEMM_SMEM);
    cudaFuncSetAttribute(gemm_hmma3<29>, cudaFuncAttributeMaxDynamicSharedMemorySize, GEMM_SMEM);
    cudaFuncSetAttribute(gemm_hmma3<25>, cudaFuncAttributeMaxDynamicSharedMemorySize, GEMM_SMEM);
    const int ATTN_SMEM = 3 * 64 * APAD * (int)sizeof(float);
    cudaFuncSetAttribute(attn_kernel, cudaFuncAttributeMaxDynamicSharedMemorySize, ATTN_SMEM);

    // weight conversions (fp32 -> bf16 hi/lo)
    {
        int n4;
        n4 = NL * DQKV * DMODEL / 4;
        f2bf_split_kernel<<<(n4 + 255) / 256, 256>>>((const float4*)attn_w,
                                                     (uint2*)wqh, (uint2*)wql, n4);
        n4 = NL * DMODEL * DMODEL / 4;
        f2bf_split_kernel<<<(n4 + 255) / 256, 256>>>((const float4*)attn_out_w,
                                                     (uint2*)waoh, (uint2*)waol, n4);
        n4 = NL * DFF * DMODEL / 4;
        f2bf_split_kernel<<<(n4 + 255) / 256, 256>>>((const float4*)mlp_in_w,
                                                     (uint2*)wmih, (uint2*)wmil, n4);
        n4 = NL * DMODEL * DFF / 4;
        f2bf_split_kernel<<<(n4 + 255) / 256, 256>>>((const float4*)mlp_out_w,
                                                     (uint2*)wmoh, (uint2*)wmol, n4);
        n4 = 4 * DMODEL * 2 * DMODEL / 4;
        f2bf_split_kernel<<<(n4 + 255) / 256, 256>>>((const float4*)skip_w,
                                                     (uint2*)wskh, (uint2*)wskl, n4);
    }
    {
        const int n4 = TOK * DMODEL / 4;
        initx_kernel<<<(n4 + 255) / 256, 256>>>((const float4*)x_in, (float4*)gx,
                                                (uint2*)xh, (uint2*)xl, n4);
    }

    const size_t XBYTES = sizeof(float) * (size_t)TOK * DMODEL;

    for (int i = 0; i < NL; i++) {
        if (i >= 5) {
            float* sv = (i == 5) ? gs4 : (i == 6) ? gs3 : gs2;
            concat_split_kernel<<<(TOK * DMODEL) / 256, 256>>>(gx, sv, xch, xcl);
            const int j = i - 4;
            gemm_hmma3<25><<<dim3(DMODEL / 128, TOK / 128), 256, GEMM_SMEM>>>(
                xch, xcl,
                wskh + (size_t)j * DMODEL * 2 * DMODEL,
                wskl + (size_t)j * DMODEL * 2 * DMODEL,
                skip_b + (size_t)j * DMODEL, nullptr, gx, xh, xl,
                DMODEL, 2 * DMODEL);
        }
        // QKV (fp32 out for attention)
        gemm_hmma3<16><<<dim3(DQKV / 128, TOK / 128), 256, GEMM_SMEM>>>(
            xh, xl,
            wqh + (size_t)i * DQKV * DMODEL, wql + (size_t)i * DQKV * DMODEL,
            nullptr, nullptr, gqkv, nullptr, nullptr, DQKV, DMODEL);
        // attention (fp32 -> bf16 hi/lo)
        attn_kernel<<<dim3(16, 16, 2), 256, ATTN_SMEM>>>(gqkv, ath, atl);
        // attn out proj + residual -> x (fp32 + hi/lo)
        gemm_hmma3<28><<<dim3(DMODEL / 128, TOK / 128), 256, GEMM_SMEM>>>(
            ath, atl,
            waoh + (size_t)i * DMODEL * DMODEL, waol + (size_t)i * DMODEL * DMODEL,
            nullptr, gx, gx, xh, xl, DMODEL, DMODEL);
        // MLP LN -> hi/lo
        ln_kernel2<true><<<TOK, 256>>>(gx, mlp_ln_g + (size_t)i * DMODEL,
                                       nullptr, lnh, lnl);
        // MLP in + bias + gelu -> hi/lo only
        gemm_hmma3<11><<<dim3(DFF / 128, TOK / 128), 256, GEMM_SMEM>>>(
            lnh, lnl,
            wmih + (size_t)i * DFF * DMODEL, wmil + (size_t)i * DFF * DMODEL,
            mlp_in_b + (size_t)i * DFF, nullptr, nullptr, ffh, ffl, DFF, DMODEL);
        // MLP out + bias + residual -> x (fp32 + hi/lo)
        gemm_hmma3<29><<<dim3(DMODEL / 128, TOK / 128), 256, GEMM_SMEM>>>(
            ffh, ffl,
            wmoh + (size_t)i * DMODEL * DFF, wmol + (size_t)i * DMODEL * DFF,
            mlp_out_b + (size_t)i * DMODEL, gx, gx, xh, xl, DMODEL, DFF);

        if (i == 2) cudaMemcpyAsync(gs2, gx, XBYTES, cudaMemcpyDeviceToDevice, 0);
        if (i == 3) cudaMemcpyAsync(gs3, gx, XBYTES, cudaMemcpyDeviceToDevice, 0);
        if (i == 4) cudaMemcpyAsync(gs4, gx, XBYTES, cudaMemcpyDeviceToDevice, 0);
    }

    ln_kernel2<false><<<TOK, 256>>>(gx, out_ln_g, (float*)d_out, nullptr, nullptr);
}

// round 5
// speedup vs baseline: 2.4111x; 1.2008x over previous
#include <cuda_runtime.h>
#include <cuda_bf16.h>
#include <math.h>
#include <stdint.h>

// ---------------- problem constants ----------------
#define TOK    2048
#define DMODEL 1024
#define DQKV   3072
#define DFF    4096
#define NL     8

// ---------------- scratch (device globals, no allocs) ----------------
__device__ float g_x   [TOK * DMODEL];
__device__ float g_sv2 [TOK * DMODEL];
__device__ float g_sv3 [TOK * DMODEL];
__device__ float g_sv4 [TOK * DMODEL];

// activation hi/lo pairs
__device__ __nv_bfloat16 a_x_h   [TOK * DMODEL];
__device__ __nv_bfloat16 a_x_l   [TOK * DMODEL];
__device__ __nv_bfloat16 a_qkv_h [TOK * DQKV];
__device__ __nv_bfloat16 a_qkv_l [TOK * DQKV];
__device__ __nv_bfloat16 a_at_h  [TOK * DMODEL];
__device__ __nv_bfloat16 a_at_l  [TOK * DMODEL];
__device__ __nv_bfloat16 a_ln_h  [TOK * DMODEL];
__device__ __nv_bfloat16 a_ln_l  [TOK * DMODEL];
__device__ __nv_bfloat16 a_ff_h  [TOK * DFF];
__device__ __nv_bfloat16 a_ff_l  [TOK * DFF];
__device__ __nv_bfloat16 a_xc_h  [TOK * 2 * DMODEL];
__device__ __nv_bfloat16 a_xc_l  [TOK * 2 * DMODEL];

// weight hi/lo pairs
__device__ __nv_bfloat16 w_qkv_h[NL * DQKV * DMODEL];
__device__ __nv_bfloat16 w_qkv_l[NL * DQKV * DMODEL];
__device__ __nv_bfloat16 w_ao_h [NL * DMODEL * DMODEL];
__device__ __nv_bfloat16 w_ao_l [NL * DMODEL * DMODEL];
__device__ __nv_bfloat16 w_mi_h [NL * DFF * DMODEL];
__device__ __nv_bfloat16 w_mi_l [NL * DFF * DMODEL];
__device__ __nv_bfloat16 w_mo_h [NL * DMODEL * DFF];
__device__ __nv_bfloat16 w_mo_l [NL * DMODEL * DFF];
__device__ __nv_bfloat16 w_sk_h [4 * DMODEL * 2 * DMODEL];
__device__ __nv_bfloat16 w_sk_l [4 * DMODEL * 2 * DMODEL];

// ---------------- helpers ----------------
__device__ __forceinline__ uint32_t smem_u32(const void* p) {
    uint32_t a;
    asm("{ .reg .u64 t; cvta.to.shared.u64 t, %1; cvt.u32.u64 %0, t; }"
        : "=r"(a) : "l"(p));
    return a;
}

__device__ __forceinline__ void cp16(uint32_t dst, const void* src) {
    asm volatile("cp.async.cg.shared.global [%0], [%1], 16;" :: "r"(dst), "l"(src));
}

__device__ __forceinline__ void ldm_x4(uint32_t addr, uint32_t& r0, uint32_t& r1,
                                       uint32_t& r2, uint32_t& r3) {
    asm volatile("ldmatrix.sync.aligned.m8n8.x4.shared.b16 {%0,%1,%2,%3}, [%4];"
                 : "=r"(r0), "=r"(r1), "=r"(r2), "=r"(r3) : "r"(addr));
}

__device__ __forceinline__ void ldm_x4t(uint32_t addr, uint32_t& r0, uint32_t& r1,
                                        uint32_t& r2, uint32_t& r3) {
    asm volatile("ldmatrix.sync.aligned.m8n8.x4.trans.shared.b16 {%0,%1,%2,%3}, [%4];"
                 : "=r"(r0), "=r"(r1), "=r"(r2), "=r"(r3) : "r"(addr));
}

__device__ __forceinline__ void mma16816(float* c, const uint32_t* a,
                                         uint32_t b0, uint32_t b1) {
    asm volatile(
        "mma.sync.aligned.m16n8k16.row.col.f32.bf16.bf16.f32 "
        "{%0,%1,%2,%3}, {%4,%5,%6,%7}, {%8,%9}, {%0,%1,%2,%3};"
        : "+f"(c[0]), "+f"(c[1]), "+f"(c[2]), "+f"(c[3])
        : "r"(a[0]), "r"(a[1]), "r"(a[2]), "r"(a[3]), "r"(b0), "r"(b1));
}

__device__ __forceinline__ void split2(float v, uint16_t& h, uint16_t& l) {
    __nv_bfloat16 hb = __float2bfloat16_rn(v);
    __nv_bfloat16 lb = __float2bfloat16_rn(v - __bfloat162float(hb));
    h = *(uint16_t*)&hb;
    l = *(uint16_t*)&lb;
}

// ---------------- bf16x3 HMMA GEMM ----------------
// FLAGS: 1=bias, 2=gelu, 4=residual(fp32), 8=write bf16 hi/lo, 16=write fp32
#define GBK     32
#define GROWB   80
#define GTILEB  (128 * GROWB)
#define GSTRIDE (4 * GTILEB)
#define GNST    4
#define GEMM_SMEM (GNST * GSTRIDE)

template<int FLAGS>
__global__ void __launch_bounds__(256) gemm_hmma3(
    const __nv_bfloat16* __restrict__ Ah, const __nv_bfloat16* __restrict__ Al,
    const __nv_bfloat16* __restrict__ Wh, const __nv_bfloat16* __restrict__ Wl,
    const float* __restrict__ bias, const float* __restrict__ res,
    float* __restrict__ C, __nv_bfloat16* __restrict__ Cbh,
    __nv_bfloat16* __restrict__ Cbl, int N, int K)
{
    extern __shared__ char smem[];
    const uint32_t sb = smem_u32(smem);
    const int tid  = threadIdx.x;
    const int wid  = tid >> 5;
    const int lane = tid & 31;
    const int wm   = wid >> 2;
    const int wn   = wid & 3;
    const int bm   = blockIdx.y * 128;
    const int bn   = blockIdx.x * 128;

    const int ldrow = tid >> 1;
    const int ldc   = (tid & 1) * 2;
    const size_t arow = (size_t)(bm + ldrow) * K + ldc * 8;
    const size_t wrow = (size_t)(bn + ldrow) * K + ldc * 8;
    const uint32_t sArow = ldrow * GROWB + ldc * 16;

    auto load_stage = [&](int s) {
        const uint32_t base = sb + (s & (GNST - 1)) * GSTRIDE;
        const size_t ko = (size_t)s * GBK;
        cp16(base + sArow,                    Ah + arow + ko);
        cp16(base + sArow + 16,               Ah + arow + ko + 8);
        cp16(base + GTILEB + sArow,           Al + arow + ko);
        cp16(base + GTILEB + sArow + 16,      Al + arow + ko + 8);
        cp16(base + 2 * GTILEB + sArow,       Wh + wrow + ko);
        cp16(base + 2 * GTILEB + sArow + 16,  Wh + wrow + ko + 8);
        cp16(base + 3 * GTILEB + sArow,       Wl + wrow + ko);
        cp16(base + 3 * GTILEB + sArow + 16,  Wl + wrow + ko + 8);
        asm volatile("cp.async.commit_group;");
    };

    const int S = K / GBK;
    for (int s = 0; s < GNST - 1; s++) load_stage(s);

    float acc[4][4][4];
#pragma unroll
    for (int i = 0; i < 4; i++)
#pragma unroll
        for (int j = 0; j < 4; j++)
#pragma unroll
            for (int k = 0; k < 4; k++) acc[i][j][k] = 0.f;

    const uint32_t aoff = (uint32_t)(wm * 64 + (lane & 15)) * GROWB + (lane >> 4) * 16;
    const uint32_t boff = (uint32_t)(wn * 32 + (lane & 7) + ((lane >> 4) & 1) * 8) * GROWB
                        + ((lane >> 3) & 1) * 16;

    for (int s = 0; s < S; s++) {
        asm volatile("cp.async.wait_group 2;" ::: "memory");
        __syncthreads();

        const int pf = s + GNST - 1;
        if (pf < S) load_stage(pf);
        else        asm volatile("cp.async.commit_group;");

        const uint32_t base = sb + (s & (GNST - 1)) * GSTRIDE;
#pragma unroll
        for (int k16 = 0; k16 < 2; k16++) {
            uint32_t ah[4][4], al[4][4], bh[2][4], bl[2][4];
#pragma unroll
            for (int fm = 0; fm < 4; fm++) {
                const uint32_t ao = aoff + fm * 16 * GROWB + k16 * 32;
                ldm_x4(base + ao,          ah[fm][0], ah[fm][1], ah[fm][2], ah[fm][3]);
                ldm_x4(base + GTILEB + ao, al[fm][0], al[fm][1], al[fm][2], al[fm][3]);
            }
#pragma unroll
            for (int fnp = 0; fnp < 2; fnp++) {
                const uint32_t bo = boff + fnp * 16 * GROWB + k16 * 32;
                ldm_x4(base + 2 * GTILEB + bo, bh[fnp][0], bh[fnp][1], bh[fnp][2], bh[fnp][3]);
                ldm_x4(base + 3 * GTILEB + bo, bl[fnp][0], bl[fnp][1], bl[fnp][2], bl[fnp][3]);
            }
#pragma unroll
            for (int fm = 0; fm < 4; fm++) {
#pragma unroll
                for (int fnp = 0; fnp < 2; fnp++) {
                    float* c0 = acc[fm][fnp * 2 + 0];
                    float* c1 = acc[fm][fnp * 2 + 1];
                    mma16816(c0, ah[fm], bh[fnp][0], bh[fnp][1]);
                    mma16816(c0, al[fm], bh[fnp][0], bh[fnp][1]);
                    mma16816(c0, ah[fm], bl[fnp][0], bl[fnp][1]);
                    mma16816(c1, ah[fm], bh[fnp][2], bh[fnp][3]);
                    mma16816(c1, al[fm], bh[fnp][2], bh[fnp][3]);
                    mma16816(c1, ah[fm], bl[fnp][2], bl[fnp][3]);
                }
            }
        }
    }

    // ---- epilogue ----
#pragma unroll
    for (int fm = 0; fm < 4; fm++) {
#pragma unroll
        for (int fn = 0; fn < 4; fn++) {
            const int r0 = bm + wm * 64 + fm * 16 + (lane >> 2);
            const int c0 = bn + wn * 32 + fn * 8 + (lane & 3) * 2;
            float v[4] = { acc[fm][fn][0], acc[fm][fn][1],
                           acc[fm][fn][2], acc[fm][fn][3] };
            if (FLAGS & 1) {
                const float b0 = __ldg(bias + c0), b1 = __ldg(bias + c0 + 1);
                v[0] += b0; v[1] += b1; v[2] += b0; v[3] += b1;
            }
            if (FLAGS & 2) {
#pragma unroll
                for (int u = 0; u < 4; u++)
                    v[u] = 0.5f * v[u] * (1.f + erff(v[u] * 0.7071067811865476f));
            }
            if (FLAGS & 4) {
                const float2 ra = *(const float2*)(res + (size_t)r0 * N + c0);
                const float2 rb = *(const float2*)(res + (size_t)(r0 + 8) * N + c0);
                v[0] += ra.x; v[1] += ra.y; v[2] += rb.x; v[3] += rb.y;
            }
            if (FLAGS & 16) {
                float2 oa; oa.x = v[0]; oa.y = v[1];
                float2 ob; ob.x = v[2]; ob.y = v[3];
                *(float2*)(C + (size_t)r0 * N + c0) = oa;
                *(float2*)(C + (size_t)(r0 + 8) * N + c0) = ob;
            }
            if (FLAGS & 8) {
                uint16_t h0, l0, h1, l1;
                split2(v[0], h0, l0); split2(v[1], h1, l1);
                uint32_t ph = (uint32_t)h0 | ((uint32_t)h1 << 16);
                uint32_t pl = (uint32_t)l0 | ((uint32_t)l1 << 16);
                *(uint32_t*)(Cbh + (size_t)r0 * N + c0) = ph;
                *(uint32_t*)(Cbl + (size_t)r0 * N + c0) = pl;
                split2(v[2], h0, l0); split2(v[3], h1, l1);
                ph = (uint32_t)h0 | ((uint32_t)h1 << 16);
                pl = (uint32_t)l0 | ((uint32_t)l1 << 16);
                *(uint32_t*)(Cbh + (size_t)(r0 + 8) * N + c0) = ph;
                *(uint32_t*)(Cbl + (size_t)(r0 + 8) * N + c0) = pl;
            }
        }
    }
}

// ---------------- HMMA flash attention (bf16x3, fp32 softmax) ----------------
// grid (16 qtiles, 16 heads, 2 batch), 128 threads (4 warps x 16 q-rows).
#define ASTR 144                 // bytes per 64-col bf16 row (conflict-free ldmatrix)
#define ATB  (64 * ASTR)         // 9216 B per 64x64 tile
#define ATTN_SMEM (10 * ATB)     // Qh,Ql + 2 x (Kh,Kl,Vh,Vl) = 92160 B

__global__ void __launch_bounds__(128) attn_hmma(
    const __nv_bfloat16* __restrict__ qh, const __nv_bfloat16* __restrict__ ql,
    __nv_bfloat16* __restrict__ out_h, __nv_bfloat16* __restrict__ out_l)
{
    extern __shared__ char smc[];
    const uint32_t sb = smem_u32(smc);
    const int b = blockIdx.z, h = blockIdx.y, q0 = blockIdx.x * 64;
    const int tid = threadIdx.x, wid = tid >> 5, lane = tid & 31;
    const float slope = -exp2f(-0.5f * (float)(h + 1));
    const size_t base = (size_t)b * 1024 * DQKV + (size_t)h * 64;

    // ---- Q load (hi at 0, lo at ATB) ----
    {
        const int which = tid >> 6, r = tid & 63;
        const __nv_bfloat16* src = (which ? ql : qh) + base + (size_t)(q0 + r) * DQKV;
        const uint32_t dst = sb + which * ATB + r * ASTR;
#pragma unroll
        for (int c = 0; c < 8; c++) cp16(dst + c * 16, src + c * 8);
        asm volatile("cp.async.commit_group;");
    }

    // KV loader: warp w fills sub-tile w of buffer (t&1): {Kh,Kl,Vh,Vl}
    auto load_kv = [&](int t) {
        const uint32_t bufb = sb + 2 * ATB + (t & 1) * (4 * ATB) + wid * ATB;
        const __nv_bfloat16* sp = ((wid & 1) ? ql : qh) + base + ((wid < 2) ? 1024 : 2048);
#pragma unroll
        for (int rr = 0; rr < 2; rr++) {
            const int r = lane + rr * 32;
            const __nv_bfloat16* src = sp + (size_t)(t * 64 + r) * DQKV;
            const uint32_t dst = bufb + r * ASTR;
#pragma unroll
            for (int c = 0; c < 8; c++) cp16(dst + c * 16, src + c * 8);
        }
        asm volatile("cp.async.commit_group;");
    };

    load_kv(0);
    asm volatile("cp.async.wait_group 0;" ::: "memory");
    __syncthreads();

    // ---- Q fragments in regs, scaled by 0.125 (exact pow2: split stays exact) ----
    uint32_t qfh[4][4], qfl[4][4];
    {
        const uint32_t ao = sb + (uint32_t)(wid * 16 + (lane & 15)) * ASTR + (lane >> 4) * 16;
#pragma unroll
        for (int kk = 0; kk < 4; kk++) {
            ldm_x4(ao + kk * 32,       qfh[kk][0], qfh[kk][1], qfh[kk][2], qfh[kk][3]);
            ldm_x4(ao + ATB + kk * 32, qfl[kk][0], qfl[kk][1], qfl[kk][2], qfl[kk][3]);
        }
        const __nv_bfloat162 sc = __float2bfloat162_rn(0.125f);
#pragma unroll
        for (int kk = 0; kk < 4; kk++)
#pragma unroll
            for (int u = 0; u < 4; u++) {
                __nv_bfloat162 vh = *(__nv_bfloat162*)&qfh[kk][u];
                __nv_bfloat162 vl = *(__nv_bfloat162*)&qfl[kk][u];
                vh = __hmul2(vh, sc); vl = __hmul2(vl, sc);
                qfh[kk][u] = *(uint32_t*)&vh; qfl[kk][u] = *(uint32_t*)&vl;
            }
    }

    const int rA = q0 + wid * 16 + (lane >> 2);
    const int rB = rA + 8;
    const bool okA = rA < 1023, okB = rB < 1023;

    float m0 = -1e30f, m1 = -1e30f, l0s = 0.f, l1s = 0.f;
    float oacc[8][4];
#pragma unroll
    for (int j = 0; j < 8; j++)
#pragma unroll
        for (int u = 0; u < 4; u++) oacc[j][u] = 0.f;

    for (int t = 0; t < 16; t++) {
        if (t > 0) {
            asm volatile("cp.async.wait_group 0;" ::: "memory");
            __syncthreads();
        }
        if (t < 15) load_kv(t + 1);

        const uint32_t kb = sb + 2 * ATB + (t & 1) * (4 * ATB);  // Kh; Kl=+ATB
        const uint32_t vb = kb + 2 * ATB;                         // Vh; Vl=+ATB

        // ---- scores = (Q*0.125) K^T via bf16x3 ----
        float s[8][4];
#pragma unroll
        for (int j = 0; j < 8; j++)
#pragma unroll
            for (int u = 0; u < 4; u++) s[j][u] = 0.f;

        const uint32_t bbase = kb + (uint32_t)((lane & 7) + ((lane >> 4) & 1) * 8) * ASTR
                             + ((lane >> 3) & 1) * 16;
#pragma unroll
        for (int kk = 0; kk < 4; kk++) {
#pragma unroll
            for (int nb = 0; nb < 4; nb++) {
                uint32_t b0, b1, b2, b3, c0, c1, c2, c3;
                const uint32_t ad = bbase + nb * 16 * ASTR + kk * 32;
                ldm_x4(ad,       b0, b1, b2, b3);
                ldm_x4(ad + ATB, c0, c1, c2, c3);
                mma16816(s[nb*2],   qfh[kk], b0, b1);
                mma16816(s[nb*2],   qfl[kk], b0, b1);
                mma16816(s[nb*2],   qfh[kk], c0, c1);
                mma16816(s[nb*2+1], qfh[kk], b2, b3);
                mma16816(s[nb*2+1], qfl[kk], b2, b3);
                mma16816(s[nb*2+1], qfh[kk], c2, c3);
            }
        }

        // ---- alibi + online softmax (fp32) ----
        float tmax0 = -1e30f, tmax1 = -1e30f;
#pragma unroll
        for (int j = 0; j < 8; j++) {
            const int kj = t * 64 + j * 8 + (lane & 3) * 2;
            const bool k0ok = kj < 1023, k1ok = kj + 1 < 1023;
            s[j][0] += (okA && k0ok) ? slope * fabsf((float)(rA - kj))     : 0.f;
            s[j][1] += (okA && k1ok) ? slope * fabsf((float)(rA - kj - 1)) : 0.f;
            s[j][2] += (okB && k0ok) ? slope * fabsf((float)(rB - kj))     : 0.f;
            s[j][3] += (okB && k1ok) ? slope * fabsf((float)(rB - kj - 1)) : 0.f;
            tmax0 = fmaxf(tmax0, fmaxf(s[j][0], s[j][1]));
            tmax1 = fmaxf(tmax1, fmaxf(s[j][2], s[j][3]));
        }
        tmax0 = fmaxf(tmax0, __shfl_xor_sync(0xffffffffu, tmax0, 1));
        tmax0 = fmaxf(tmax0, __shfl_xor_sync(0xffffffffu, tmax0, 2));
        tmax1 = fmaxf(tmax1, __shfl_xor_sync(0xffffffffu, tmax1, 1));
        tmax1 = fmaxf(tmax1, __shfl_xor_sync(0xffffffffu, tmax1, 2));

        const float mn0 = fmaxf(m0, tmax0), mn1 = fmaxf(m1, tmax1);
        const float al0 = __expf(m0 - mn0), al1 = __expf(m1 - mn1);
        m0 = mn0; m1 = mn1;

        float rs0 = 0.f, rs1 = 0.f;
#pragma unroll
        for (int j = 0; j < 8; j++) {
            s[j][0] = __expf(s[j][0] - mn0); rs0 += s[j][0];
            s[j][1] = __expf(s[j][1] - mn0); rs0 += s[j][1];
            s[j][2] = __expf(s[j][2] - mn1); rs1 += s[j][2];
            s[j][3] = __expf(s[j][3] - mn1); rs1 += s[j][3];
        }
        rs0 += __shfl_xor_sync(0xffffffffu, rs0, 1);
        rs0 += __shfl_xor_sync(0xffffffffu, rs0, 2);
        rs1 += __shfl_xor_sync(0xffffffffu, rs1, 1);
        rs1 += __shfl_xor_sync(0xffffffffu, rs1, 2);
        l0s = l0s * al0 + rs0;
        l1s = l1s * al1 + rs1;
#pragma unroll
        for (int j = 0; j < 8; j++) {
            oacc[j][0] *= al0; oacc[j][1] *= al0;
            oacc[j][2] *= al1; oacc[j][3] *= al1;
        }

        // ---- pack P hi/lo into A-fragments (C-frag layout == A-frag layout) ----
        uint32_t pfh[4][4], pfl[4][4];
#pragma unroll
        for (int kk = 0; kk < 4; kk++) {
#pragma unroll
            for (int half = 0; half < 2; half++) {
                const int j = 2 * kk + half;
                uint16_t h0, l0, h1, l1, h2, l2, h3, l3;
                split2(s[j][0], h0, l0); split2(s[j][1], h1, l1);
                split2(s[j][2], h2, l2); split2(s[j][3], h3, l3);
                pfh[kk][half*2+0] = (uint32_t)h0 | ((uint32_t)h1 << 16);
                pfh[kk][half*2+1] = (uint32_t)h2 | ((uint32_t)h3 << 16);
                pfl[kk][half*2+0] = (uint32_t)l0 | ((uint32_t)l1 << 16);
                pfl[kk][half*2+1] = (uint32_t)l2 | ((uint32_t)l3 << 16);
            }
        }

        // ---- O += P V via bf16x3 (V loaded transposed with ldmatrix.trans) ----
        const uint32_t vbase = vb + (uint32_t)(((lane >> 3) & 1) * 8 + (lane & 7)) * ASTR
                             + (lane >> 4) * 16;
#pragma unroll
        for (int kk = 0; kk < 4; kk++) {
#pragma unroll
            for (int nb = 0; nb < 4; nb++) {
                uint32_t v0, v1, v2, v3, w0, w1, w2, w3;
                const uint32_t ad = vbase + kk * 16 * ASTR + nb * 32;
                ldm_x4t(ad,       v0, v1, v2, v3);
                ldm_x4t(ad + ATB, w0, w1, w2, w3);
                mma16816(oacc[nb*2],   pfh[kk], v0, v1);
                mma16816(oacc[nb*2],   pfl[kk], v0, v1);
                mma16816(oacc[nb*2],   pfh[kk], w0, w1);
                mma16816(oacc[nb*2+1], pfh[kk], v2, v3);
                mma16816(oacc[nb*2+1], pfl[kk], v2, v3);
                mma16816(oacc[nb*2+1], pfh[kk], w2, w3);
            }
        }
    }

    // ---- normalize + write hi/lo ----
    const float inv0 = 1.f / l0s, inv1 = 1.f / l1s;
#pragma unroll
    for (int j = 0; j < 8; j++) {
        const int d0 = j * 8 + (lane & 3) * 2;
        uint16_t h0, l0, h1, l1;
        split2(oacc[j][0] * inv0, h0, l0); split2(oacc[j][1] * inv0, h1, l1);
        size_t o = ((size_t)b * 1024 + rA) * DMODEL + h * 64 + d0;
        *(uint32_t*)(out_h + o) = (uint32_t)h0 | ((uint32_t)h1 << 16);
        *(uint32_t*)(out_l + o) = (uint32_t)l0 | ((uint32_t)l1 << 16);
        split2(oacc[j][2] * inv1, h0, l0); split2(oacc[j][3] * inv1, h1, l1);
        o += (size_t)8 * DMODEL;
        *(uint32_t*)(out_h + o) = (uint32_t)h0 | ((uint32_t)h1 << 16);
        *(uint32_t*)(out_l + o) = (uint32_t)l0 | ((uint32_t)l1 << 16);
    }
}

// ---------------- LayerNorm ----------------
template<bool BF>
__global__ void __launch_bounds__(256) ln_kernel2(
    const float* __restrict__ x, const float* __restrict__ g,
    float* __restrict__ y,
    __nv_bfloat16* __restrict__ yh, __nv_bfloat16* __restrict__ yl)
{
    __shared__ float red[256];
    const int row = blockIdx.x;
    const int tid = threadIdx.x;
    const float* xr = x + (size_t)row * DMODEL;

    float v[4];
    float s = 0.f;
#pragma unroll
    for (int u = 0; u < 4; u++) { v[u] = xr[tid + u * 256]; s += v[u]; }
    red[tid] = s; __syncthreads();
    for (int o = 128; o; o >>= 1) {
        if (tid < o) red[tid] += red[tid + o];
        __syncthreads();
    }
    const float mu = red[0] * (1.f / 1024.f);
    __syncthreads();

    float q = 0.f;
#pragma unroll
    for (int u = 0; u < 4; u++) { const float d = v[u] - mu; q += d * d; }
    red[tid] = q; __syncthreads();
    for (int o = 128; o; o >>= 1) {
        if (tid < o) red[tid] += red[tid + o];
        __syncthreads();
    }
    const float r = rsqrtf(red[0] * (1.f / 1024.f) + 1e-5f);

#pragma unroll
    for (int u = 0; u < 4; u++) {
        const float val = (v[u] - mu) * r * g[tid + u * 256];
        const size_t o = (size_t)row * DMODEL + tid + u * 256;
        if (BF) {
            uint16_t h0, l0;
            split2(val, h0, l0);
            *(uint16_t*)(yh + o) = h0;
            *(uint16_t*)(yl + o) = l0;
        } else {
            y[o] = val;
        }
    }
}

// ---------------- skip concat ----------------
__global__ void __launch_bounds__(256) concat_split_kernel(
    const float* __restrict__ x, const float* __restrict__ s,
    __nv_bfloat16* __restrict__ xch, __nv_bfloat16* __restrict__ xcl)
{
    const int idx = blockIdx.x * blockDim.x + threadIdx.x;
    const int row = idx >> 10;
    const int col = idx & 1023;
    const size_t b = (size_t)row * (2 * DMODEL);
    uint16_t h0, l0;
    split2(x[idx], h0, l0);
    *(uint16_t*)(xch + b + col) = h0;
    *(uint16_t*)(xcl + b + col) = l0;
    split2(s[idx] * 0.70710678118654752440f, h0, l0);
    *(uint16_t*)(xch + b + DMODEL + col) = h0;
    *(uint16_t*)(xcl + b + DMODEL + col) = l0;
}

// ---------------- fp32 -> bf16 hi/lo converters ----------------
__global__ void __launch_bounds__(256) f2bf_split_kernel(
    const float4* __restrict__ in, uint2* __restrict__ oh,
    uint2* __restrict__ ol, int n4)
{
    const int i = blockIdx.x * blockDim.x + threadIdx.x;
    if (i < n4) {
        float4 v = in[i];
        uint16_t h[4], l[4];
        split2(v.x, h[0], l[0]); split2(v.y, h[1], l[1]);
        split2(v.z, h[2], l[2]); split2(v.w, h[3], l[3]);
        uint2 uh, ul;
        uh.x = (uint32_t)h[0] | ((uint32_t)h[1] << 16);
        uh.y = (uint32_t)h[2] | ((uint32_t)h[3] << 16);
        ul.x = (uint32_t)l[0] | ((uint32_t)l[1] << 16);
        ul.y = (uint32_t)l[2] | ((uint32_t)l[3] << 16);
        oh[i] = uh; ol[i] = ul;
    }
}

__global__ void __launch_bounds__(256) initx_kernel(
    const float4* __restrict__ in, float4* __restrict__ xf,
    uint2* __restrict__ xh, uint2* __restrict__ xl, int n4)
{
    const int i = blockIdx.x * blockDim.x + threadIdx.x;
    if (i < n4) {
        float4 v = in[i];
        xf[i] = v;
        uint16_t h[4], l[4];
        split2(v.x, h[0], l[0]); split2(v.y, h[1], l[1]);
        split2(v.z, h[2], l[2]); split2(v.w, h[3], l[3]);
        uint2 uh, ul;
        uh.x = (uint32_t)h[0] | ((uint32_t)h[1] << 16);
        uh.y = (uint32_t)h[2] | ((uint32_t)h[3] << 16);
        ul.x = (uint32_t)l[0] | ((uint32_t)l[1] << 16);
        ul.y = (uint32_t)l[2] | ((uint32_t)l[3] << 16);
        xh[i] = uh; xl[i] = ul;
    }
}

// ---------------- host orchestration ----------------
extern "C" void kernel_launch(void* const* d_in, const int* in_sizes, int n_in,
                              void* d_out, int out_size)
{
    (void)in_sizes; (void)n_in; (void)out_size;
    const float* x_in       = (const float*)d_in[0];
    const float* attn_w     = (const float*)d_in[1];
    const float* attn_out_w = (const float*)d_in[2];
    const float* mlp_ln_g   = (const float*)d_in[3];
    const float* mlp_in_w   = (const float*)d_in[4];
    const float* mlp_in_b   = (const float*)d_in[5];
    const float* mlp_out_w  = (const float*)d_in[6];
    const float* mlp_out_b  = (const float*)d_in[7];
    const float* skip_w     = (const float*)d_in[8];
    const float* skip_b     = (const float*)d_in[9];
    const float* out_ln_g   = (const float*)d_in[10];

    float *gx, *gs2, *gs3, *gs4;
    cudaGetSymbolAddress((void**)&gx,  g_x);
    cudaGetSymbolAddress((void**)&gs2, g_sv2);
    cudaGetSymbolAddress((void**)&gs3, g_sv3);
    cudaGetSymbolAddress((void**)&gs4, g_sv4);

    __nv_bfloat16 *xh, *xl, *qkvh, *qkvl, *ath, *atl, *lnh, *lnl, *ffh, *ffl, *xch, *xcl;
    cudaGetSymbolAddress((void**)&xh,   a_x_h);   cudaGetSymbolAddress((void**)&xl,   a_x_l);
    cudaGetSymbolAddress((void**)&qkvh, a_qkv_h); cudaGetSymbolAddress((void**)&qkvl, a_qkv_l);
    cudaGetSymbolAddress((void**)&ath,  a_at_h);  cudaGetSymbolAddress((void**)&atl,  a_at_l);
    cudaGetSymbolAddress((void**)&lnh,  a_ln_h);  cudaGetSymbolAddress((void**)&lnl,  a_ln_l);
    cudaGetSymbolAddress((void**)&ffh,  a_ff_h);  cudaGetSymbolAddress((void**)&ffl,  a_ff_l);
    cudaGetSymbolAddress((void**)&xch,  a_xc_h);  cudaGetSymbolAddress((void**)&xcl,  a_xc_l);

    __nv_bfloat16 *wqh, *wql, *waoh, *waol, *wmih, *wmil, *wmoh, *wmol, *wskh, *wskl;
    cudaGetSymbolAddress((void**)&wqh,  w_qkv_h); cudaGetSymbolAddress((void**)&wql,  w_qkv_l);
    cudaGetSymbolAddress((void**)&waoh, w_ao_h);  cudaGetSymbolAddress((void**)&waol, w_ao_l);
    cudaGetSymbolAddress((void**)&wmih, w_mi_h);  cudaGetSymbolAddress((void**)&wmil, w_mi_l);
    cudaGetSymbolAddress((void**)&wmoh, w_mo_h);  cudaGetSymbolAddress((void**)&wmol, w_mo_l);
    cudaGetSymbolAddress((void**)&wskh, w_sk_h);  cudaGetSymbolAddress((void**)&wskl, w_sk_l);

    cudaFuncSetAttribute(gemm_hmma3<8>,  cudaFuncAttributeMaxDynamicSharedMemorySize, GEMM_SMEM);
    cudaFuncSetAttribute(gemm_hmma3<28>, cudaFuncAttributeMaxDynamicSharedMemorySize, GEMM_SMEM);
    cudaFuncSetAttribute(gemm_hmma3<11>, cudaFuncAttributeMaxDynamicSharedMemorySize, GEMM_SMEM);
    cudaFuncSetAttribute(gemm_hmma3<29>, cudaFuncAttributeMaxDynamicSharedMemorySize, GEMM_SMEM);
    cudaFuncSetAttribute(gemm_hmma3<25>, cudaFuncAttributeMaxDynamicSharedMemorySize, GEMM_SMEM);
    cudaFuncSetAttribute(attn_hmma, cudaFuncAttributeMaxDynamicSharedMemorySize, ATTN_SMEM);

    // weight conversions (fp32 -> bf16 hi/lo)
    {
        int n4;
        n4 = NL * DQKV * DMODEL / 4;
        f2bf_split_kernel<<<(n4 + 255) / 256, 256>>>((const float4*)attn_w,
                                                     (uint2*)wqh, (uint2*)wql, n4);
        n4 = NL * DMODEL * DMODEL / 4;
        f2bf_split_kernel<<<(n4 + 255) / 256, 256>>>((const float4*)attn_out_w,
                                                     (uint2*)waoh, (uint2*)waol, n4);
        n4 = NL * DFF * DMODEL / 4;
        f2bf_split_kernel<<<(n4 + 255) / 256, 256>>>((const float4*)mlp_in_w,
                                                     (uint2*)wmih, (uint2*)wmil, n4);
        n4 = NL * DMODEL * DFF / 4;
        f2bf_split_kernel<<<(n4 + 255) / 256, 256>>>((const float4*)mlp_out_w,
                                                     (uint2*)wmoh, (uint2*)wmol, n4);
        n4 = 4 * DMODEL * 2 * DMODEL / 4;
        f2bf_split_kernel<<<(n4 + 255) / 256, 256>>>((const float4*)skip_w,
                                                     (uint2*)wskh, (uint2*)wskl, n4);
    }
    {
        const int n4 = TOK * DMODEL / 4;
        initx_kernel<<<(n4 + 255) / 256, 256>>>((const float4*)x_in, (float4*)gx,
                                                (uint2*)xh, (uint2*)xl, n4);
    }

    const size_t XBYTES = sizeof(float) * (size_t)TOK * DMODEL;

    for (int i = 0; i < NL; i++) {
        if (i >= 5) {
            float* sv = (i == 5) ? gs4 : (i == 6) ? gs3 : gs2;
            concat_split_kernel<<<(TOK * DMODEL) / 256, 256>>>(gx, sv, xch, xcl);
            const int j = i - 4;
            gemm_hmma3<25><<<dim3(DMODEL / 128, TOK / 128), 256, GEMM_SMEM>>>(
                xch, xcl,
                wskh + (size_t)j * DMODEL * 2 * DMODEL,
                wskl + (size_t)j * DMODEL * 2 * DMODEL,
                skip_b + (size_t)j * DMODEL, nullptr, gx, xh, xl,
                DMODEL, 2 * DMODEL);
        }
        // QKV -> bf16 hi/lo
        gemm_hmma3<8><<<dim3(DQKV / 128, TOK / 128), 256, GEMM_SMEM>>>(
            xh, xl,
            wqh + (size_t)i * DQKV * DMODEL, wql + (size_t)i * DQKV * DMODEL,
            nullptr, nullptr, nullptr, qkvh, qkvl, DQKV, DMODEL);
        // HMMA flash attention -> bf16 hi/lo
        attn_hmma<<<dim3(16, 16, 2), 128, ATTN_SMEM>>>(qkvh, qkvl, ath, atl);
        // attn out proj + residual -> x (fp32 + hi/lo)
        gemm_hmma3<28><<<dim3(DMODEL / 128, TOK / 128), 256, GEMM_SMEM>>>(
            ath, atl,
            waoh + (size_t)i * DMODEL * DMODEL, waol + (size_t)i * DMODEL * DMODEL,
            nullptr, gx, gx, xh, xl, DMODEL, DMODEL);
        // MLP LN -> hi/lo
        ln_kernel2<true><<<TOK, 256>>>(gx, mlp_ln_g + (size_t)i * DMODEL,
                                       nullptr, lnh, lnl);
        // MLP in + bias + gelu -> hi/lo
        gemm_hmma3<11><<<dim3(DFF / 128, TOK / 128), 256, GEMM_SMEM>>>(
            lnh, lnl,
            wmih + (size_t)i * DFF * DMODEL, wmil + (size_t)i * DFF * DMODEL,
            mlp_in_b + (size_t)i * DFF, nullptr, nullptr, ffh, ffl, DFF, DMODEL);
        // MLP out + bias + residual -> x (fp32 + hi/lo)
        gemm_hmma3<29><<<dim3(DMODEL / 128, TOK / 128), 256, GEMM_SMEM>>>(
            ffh, ffl,
            wmoh + (size_t)i * DMODEL * DFF, wmol + (size_t)i * DMODEL * DFF,
            mlp_out_b + (size_t)i * DMODEL, gx, gx, xh, xl, DMODEL, DFF);

        if (i == 2) cudaMemcpyAsync(gs2, gx, XBYTES, cudaMemcpyDeviceToDevice, 0);
        if (i == 3) cudaMemcpyAsync(gs3, gx, XBYTES, cudaMemcpyDeviceToDevice, 0);
        if (i == 4) cudaMemcpyAsync(gs4, gx, XBYTES, cudaMemcpyDeviceToDevice, 0);
    }

    ln_kernel2<false><<<TOK, 256>>>(gx, out_ln_g, (float*)d_out, nullptr, nullptr);
}

// round 6
// speedup vs baseline: 3.0861x; 1.2800x over previous
#include <cuda_runtime.h>
#include <cuda_bf16.h>
#include <cuda_fp16.h>
#include <math.h>
#include <stdint.h>

// ---------------- problem constants ----------------
#define TOK    2048
#define DMODEL 1024
#define DQKV   3072
#define DFF    4096
#define NL     8

// ---------------- scratch (device globals, no allocs) ----------------
__device__ float g_x[TOK * DMODEL];

// x stream hi/lo (fp16), double-buffered
__device__ __half a_xA_h[TOK * DMODEL];
__device__ __half a_xA_l[TOK * DMODEL];
__device__ __half a_xB_h[TOK * DMODEL];
__device__ __half a_xB_l[TOK * DMODEL];
// saved skip connections (fp16 hi/lo)
__device__ __half s_v2_h[TOK * DMODEL];
__device__ __half s_v2_l[TOK * DMODEL];
__device__ __half s_v3_h[TOK * DMODEL];
__device__ __half s_v3_l[TOK * DMODEL];
__device__ __half s_v4_h[TOK * DMODEL];
__device__ __half s_v4_l[TOK * DMODEL];
// activations
__device__ __nv_bfloat16 a_qkv_h[TOK * DQKV];   // attention input stays bf16 (3-term)
__device__ __nv_bfloat16 a_qkv_l[TOK * DQKV];
__device__ __half a_at_h[TOK * DMODEL];
__device__ __half a_at_l[TOK * DMODEL];
__device__ __half a_ln_h[TOK * DMODEL];
__device__ __half a_ln_l[TOK * DMODEL];
__device__ __half a_ff_h[TOK * DFF];
__device__ __half a_ff_l[TOK * DFF];
// weights: single fp16
__device__ __half w_qkv[NL * DQKV * DMODEL];
__device__ __half w_ao [NL * DMODEL * DMODEL];
__device__ __half w_mi [NL * DFF * DMODEL];
__device__ __half w_mo [NL * DMODEL * DFF];
__device__ __half w_sk [4 * DMODEL * 2 * DMODEL];  // cols >=1024 pre-scaled by 2^-0.5

// ---------------- helpers ----------------
__device__ __forceinline__ uint32_t smem_u32(const void* p) {
    uint32_t a;
    asm("{ .reg .u64 t; cvta.to.shared.u64 t, %1; cvt.u32.u64 %0, t; }"
        : "=r"(a) : "l"(p));
    return a;
}

__device__ __forceinline__ void cp16(uint32_t dst, const void* src) {
    asm volatile("cp.async.cg.shared.global [%0], [%1], 16;" :: "r"(dst), "l"(src));
}

__device__ __forceinline__ void ldm_x4(uint32_t addr, uint32_t& r0, uint32_t& r1,
                                       uint32_t& r2, uint32_t& r3) {
    asm volatile("ldmatrix.sync.aligned.m8n8.x4.shared.b16 {%0,%1,%2,%3}, [%4];"
                 : "=r"(r0), "=r"(r1), "=r"(r2), "=r"(r3) : "r"(addr));
}

__device__ __forceinline__ void ldm_x4t(uint32_t addr, uint32_t& r0, uint32_t& r1,
                                        uint32_t& r2, uint32_t& r3) {
    asm volatile("ldmatrix.sync.aligned.m8n8.x4.trans.shared.b16 {%0,%1,%2,%3}, [%4];"
                 : "=r"(r0), "=r"(r1), "=r"(r2), "=r"(r3) : "r"(addr));
}

// bf16 MMA (attention)
__device__ __forceinline__ void mma_bf(float* c, const uint32_t* a,
                                       uint32_t b0, uint32_t b1) {
    asm volatile(
        "mma.sync.aligned.m16n8k16.row.col.f32.bf16.bf16.f32 "
        "{%0,%1,%2,%3}, {%4,%5,%6,%7}, {%8,%9}, {%0,%1,%2,%3};"
        : "+f"(c[0]), "+f"(c[1]), "+f"(c[2]), "+f"(c[3])
        : "r"(a[0]), "r"(a[1]), "r"(a[2]), "r"(a[3]), "r"(b0), "r"(b1));
}

// fp16 MMA (GEMMs)
__device__ __forceinline__ void mma_fp(float* c, const uint32_t* a,
                                       uint32_t b0, uint32_t b1) {
    asm volatile(
        "mma.sync.aligned.m16n8k16.row.col.f32.f16.f16.f32 "
        "{%0,%1,%2,%3}, {%4,%5,%6,%7}, {%8,%9}, {%0,%1,%2,%3};"
        : "+f"(c[0]), "+f"(c[1]), "+f"(c[2]), "+f"(c[3])
        : "r"(a[0]), "r"(a[1]), "r"(a[2]), "r"(a[3]), "r"(b0), "r"(b1));
}

__device__ __forceinline__ void split_bf(float v, uint16_t& h, uint16_t& l) {
    __nv_bfloat16 hb = __float2bfloat16_rn(v);
    __nv_bfloat16 lb = __float2bfloat16_rn(v - __bfloat162float(hb));
    h = *(uint16_t*)&hb;
    l = *(uint16_t*)&lb;
}

__device__ __forceinline__ void split_h(float v, uint16_t& h, uint16_t& l) {
    __half hb = __float2half_rn(v);
    __half lb = __float2half_rn(v - __half2float(hb));
    h = *(uint16_t*)&hb;
    l = *(uint16_t*)&lb;
}

// ---------------- fp16 2-term HMMA GEMM ----------------
// C = act(A * W^T + bias)(+res); A = Ah+Al fp16 pair, W single fp16.
// FLAGS: 1=bias, 2=gelu, 4=residual, 8=write hi/lo, 16=write fp32, 32=hi/lo is fp16
#define GBK     32
#define GROWB   80
#define GTILEB  (128 * GROWB)            // 10240 B per 128x32 tile
#define GSTRIDE (3 * GTILEB)             // Ah|Al|W per stage = 30720 B
#define GNST    4
#define GEMM_SMEM (GNST * GSTRIDE)       // 122880 B

template<int FLAGS, bool SPLITA>
__global__ void __launch_bounds__(256) gemm_f16(
    const __half* __restrict__ Ah, const __half* __restrict__ Al,
    const __half* __restrict__ A2h, const __half* __restrict__ A2l,
    const __half* __restrict__ W,
    const float* __restrict__ bias, const float* __restrict__ res,
    float* __restrict__ C, uint16_t* __restrict__ Cbh,
    uint16_t* __restrict__ Cbl, int N, int K)
{
    extern __shared__ char smem[];
    const uint32_t sb = smem_u32(smem);
    const int tid  = threadIdx.x;
    const int wid  = tid >> 5;
    const int lane = tid & 31;
    const int wm   = wid >> 2;
    const int wn   = wid & 3;
    const int bm   = blockIdx.y * 128;
    const int bn   = blockIdx.x * 128;

    const int ldrow = tid >> 1;
    const int ldc   = (tid & 1) * 2;
    const size_t arowK = (size_t)(bm + ldrow) * K + ldc * 8;       // non-split
    const size_t arow1 = (size_t)(bm + ldrow) * 1024 + ldc * 8;    // split halves
    const size_t wrow  = (size_t)(bn + ldrow) * K + ldc * 8;
    const uint32_t sArow = ldrow * GROWB + ldc * 16;

    auto load_stage = [&](int s) {
        const uint32_t base = sb + (s & (GNST - 1)) * GSTRIDE;
        const size_t ko = (size_t)s * GBK;
        const __half *pah, *pal;
        if (SPLITA) {
            if (ko >= 1024) { pah = A2h + arow1 + (ko - 1024); pal = A2l + arow1 + (ko - 1024); }
            else            { pah = Ah  + arow1 + ko;          pal = Al  + arow1 + ko; }
        } else {
            pah = Ah + arowK + ko; pal = Al + arowK + ko;
        }
        cp16(base + sArow,               pah);
        cp16(base + sArow + 16,          pah + 8);
        cp16(base + GTILEB + sArow,      pal);
        cp16(base + GTILEB + sArow + 16, pal + 8);
        const __half* pw = W + wrow + ko;
        cp16(base + 2 * GTILEB + sArow,      pw);
        cp16(base + 2 * GTILEB + sArow + 16, pw + 8);
        asm volatile("cp.async.commit_group;");
    };

    const int S = K / GBK;
    for (int s = 0; s < GNST - 1; s++) load_stage(s);

    float acc[4][4][4];
#pragma unroll
    for (int i = 0; i < 4; i++)
#pragma unroll
        for (int j = 0; j < 4; j++)
#pragma unroll
            for (int k = 0; k < 4; k++) acc[i][j][k] = 0.f;

    const uint32_t aoff = (uint32_t)(wm * 64 + (lane & 15)) * GROWB + (lane >> 4) * 16;
    const uint32_t boff = (uint32_t)(wn * 32 + (lane & 7) + ((lane >> 4) & 1) * 8) * GROWB
                        + ((lane >> 3) & 1) * 16 + 2 * GTILEB;

    for (int s = 0; s < S; s++) {
        asm volatile("cp.async.wait_group 2;" ::: "memory");
        __syncthreads();

        const int pf = s + GNST - 1;
        if (pf < S) load_stage(pf);
        else        asm volatile("cp.async.commit_group;");

        const uint32_t base = sb + (s & (GNST - 1)) * GSTRIDE;
#pragma unroll
        for (int k16 = 0; k16 < 2; k16++) {
            uint32_t ah[4][4], al[4][4], bb[2][4];
#pragma unroll
            for (int fm = 0; fm < 4; fm++) {
                const uint32_t ao = aoff + fm * 16 * GROWB + k16 * 32;
                ldm_x4(base + ao,          ah[fm][0], ah[fm][1], ah[fm][2], ah[fm][3]);
                ldm_x4(base + GTILEB + ao, al[fm][0], al[fm][1], al[fm][2], al[fm][3]);
            }
#pragma unroll
            for (int fnp = 0; fnp < 2; fnp++) {
                const uint32_t bo = boff + fnp * 16 * GROWB + k16 * 32;
                ldm_x4(base + bo, bb[fnp][0], bb[fnp][1], bb[fnp][2], bb[fnp][3]);
            }
#pragma unroll
            for (int fm = 0; fm < 4; fm++) {
#pragma unroll
                for (int fnp = 0; fnp < 2; fnp++) {
                    float* c0 = acc[fm][fnp * 2 + 0];
                    float* c1 = acc[fm][fnp * 2 + 1];
                    mma_fp(c0, ah[fm], bb[fnp][0], bb[fnp][1]);
                    mma_fp(c0, al[fm], bb[fnp][0], bb[fnp][1]);
                    mma_fp(c1, ah[fm], bb[fnp][2], bb[fnp][3]);
                    mma_fp(c1, al[fm], bb[fnp][2], bb[fnp][3]);
                }
            }
        }
    }

    // ---- epilogue ----
#pragma unroll
    for (int fm = 0; fm < 4; fm++) {
#pragma unroll
        for (int fn = 0; fn < 4; fn++) {
            const int r0 = bm + wm * 64 + fm * 16 + (lane >> 2);
            const int c0 = bn + wn * 32 + fn * 8 + (lane & 3) * 2;
            float v[4] = { acc[fm][fn][0], acc[fm][fn][1],
                           acc[fm][fn][2], acc[fm][fn][3] };
            if (FLAGS & 1) {
                const float b0 = __ldg(bias + c0), b1 = __ldg(bias + c0 + 1);
                v[0] += b0; v[1] += b1; v[2] += b0; v[3] += b1;
            }
            if (FLAGS & 2) {
#pragma unroll
                for (int u = 0; u < 4; u++)
                    v[u] = 0.5f * v[u] * (1.f + erff(v[u] * 0.7071067811865476f));
            }
            if (FLAGS & 4) {
                const float2 ra = *(const float2*)(res + (size_t)r0 * N + c0);
                const float2 rb = *(const float2*)(res + (size_t)(r0 + 8) * N + c0);
                v[0] += ra.x; v[1] += ra.y; v[2] += rb.x; v[3] += rb.y;
            }
            if (FLAGS & 16) {
                float2 oa; oa.x = v[0]; oa.y = v[1];
                float2 ob; ob.x = v[2]; ob.y = v[3];
                *(float2*)(C + (size_t)r0 * N + c0) = oa;
                *(float2*)(C + (size_t)(r0 + 8) * N + c0) = ob;
            }
            if (FLAGS & 8) {
                uint16_t h0, l0, h1, l1;
#pragma unroll
                for (int half2i = 0; half2i < 2; half2i++) {
                    const int rr = r0 + half2i * 8;
                    const float va = v[half2i * 2 + 0], vb2 = v[half2i * 2 + 1];
                    if (FLAGS & 32) { split_h(va, h0, l0);  split_h(vb2, h1, l1); }
                    else            { split_bf(va, h0, l0); split_bf(vb2, h1, l1); }
                    *(uint32_t*)(Cbh + (size_t)rr * N + c0) = (uint32_t)h0 | ((uint32_t)h1 << 16);
                    *(uint32_t*)(Cbl + (size_t)rr * N + c0) = (uint32_t)l0 | ((uint32_t)l1 << 16);
                }
            }
        }
    }
}

// ---------------- HMMA flash attention (bf16x3 inside, fp16 hi/lo out) ------
#define ASTR 144
#define ATB  (64 * ASTR)
#define ATTN_SMEM (10 * ATB)

__global__ void __launch_bounds__(128) attn_hmma(
    const __nv_bfloat16* __restrict__ qh, const __nv_bfloat16* __restrict__ ql,
    uint16_t* __restrict__ out_h, uint16_t* __restrict__ out_l)
{
    extern __shared__ char smc[];
    const uint32_t sb = smem_u32(smc);
    const int b = blockIdx.z, h = blockIdx.y, q0 = blockIdx.x * 64;
    const int tid = threadIdx.x, wid = tid >> 5, lane = tid & 31;
    const float slope = -exp2f(-0.5f * (float)(h + 1));
    const size_t base = (size_t)b * 1024 * DQKV + (size_t)h * 64;

    {
        const int which = tid >> 6, r = tid & 63;
        const __nv_bfloat16* src = (which ? ql : qh) + base + (size_t)(q0 + r) * DQKV;
        const uint32_t dst = sb + which * ATB + r * ASTR;
#pragma unroll
        for (int c = 0; c < 8; c++) cp16(dst + c * 16, src + c * 8);
        asm volatile("cp.async.commit_group;");
    }

    auto load_kv = [&](int t) {
        const uint32_t bufb = sb + 2 * ATB + (t & 1) * (4 * ATB) + wid * ATB;
        const __nv_bfloat16* sp = ((wid & 1) ? ql : qh) + base + ((wid < 2) ? 1024 : 2048);
#pragma unroll
        for (int rr = 0; rr < 2; rr++) {
            const int r = lane + rr * 32;
            const __nv_bfloat16* src = sp + (size_t)(t * 64 + r) * DQKV;
            const uint32_t dst = bufb + r * ASTR;
#pragma unroll
            for (int c = 0; c < 8; c++) cp16(dst + c * 16, src + c * 8);
        }
        asm volatile("cp.async.commit_group;");
    };

    load_kv(0);
    asm volatile("cp.async.wait_group 0;" ::: "memory");
    __syncthreads();

    uint32_t qfh[4][4], qfl[4][4];
    {
        const uint32_t ao = sb + (uint32_t)(wid * 16 + (lane & 15)) * ASTR + (lane >> 4) * 16;
#pragma unroll
        for (int kk = 0; kk < 4; kk++) {
            ldm_x4(ao + kk * 32,       qfh[kk][0], qfh[kk][1], qfh[kk][2], qfh[kk][3]);
            ldm_x4(ao + ATB + kk * 32, qfl[kk][0], qfl[kk][1], qfl[kk][2], qfl[kk][3]);
        }
        const __nv_bfloat162 sc = __float2bfloat162_rn(0.125f);
#pragma unroll
        for (int kk = 0; kk < 4; kk++)
#pragma unroll
            for (int u = 0; u < 4; u++) {
                __nv_bfloat162 vh = *(__nv_bfloat162*)&qfh[kk][u];
                __nv_bfloat162 vl = *(__nv_bfloat162*)&qfl[kk][u];
                vh = __hmul2(vh, sc); vl = __hmul2(vl, sc);
                qfh[kk][u] = *(uint32_t*)&vh; qfl[kk][u] = *(uint32_t*)&vl;
            }
    }

    const int rA = q0 + wid * 16 + (lane >> 2);
    const int rB = rA + 8;
    const bool okA = rA < 1023, okB = rB < 1023;

    float m0 = -1e30f, m1 = -1e30f, l0s = 0.f, l1s = 0.f;
    float oacc[8][4];
#pragma unroll
    for (int j = 0; j < 8; j++)
#pragma unroll
        for (int u = 0; u < 4; u++) oacc[j][u] = 0.f;

    for (int t = 0; t < 16; t++) {
        if (t > 0) {
            asm volatile("cp.async.wait_group 0;" ::: "memory");
            __syncthreads();
        }
        if (t < 15) load_kv(t + 1);

        const uint32_t kb = sb + 2 * ATB + (t & 1) * (4 * ATB);
        const uint32_t vb = kb + 2 * ATB;

        float s[8][4];
#pragma unroll
        for (int j = 0; j < 8; j++)
#pragma unroll
            for (int u = 0; u < 4; u++) s[j][u] = 0.f;

        const uint32_t bbase = kb + (uint32_t)((lane & 7) + ((lane >> 4) & 1) * 8) * ASTR
                             + ((lane >> 3) & 1) * 16;
#pragma unroll
        for (int kk = 0; kk < 4; kk++) {
#pragma unroll
            for (int nb = 0; nb < 4; nb++) {
                uint32_t b0, b1, b2, b3, c0, c1, c2, c3;
                const uint32_t ad = bbase + nb * 16 * ASTR + kk * 32;
                ldm_x4(ad,       b0, b1, b2, b3);
                ldm_x4(ad + ATB, c0, c1, c2, c3);
                mma_bf(s[nb*2],   qfh[kk], b0, b1);
                mma_bf(s[nb*2],   qfl[kk], b0, b1);
                mma_bf(s[nb*2],   qfh[kk], c0, c1);
                mma_bf(s[nb*2+1], qfh[kk], b2, b3);
                mma_bf(s[nb*2+1], qfl[kk], b2, b3);
                mma_bf(s[nb*2+1], qfh[kk], c2, c3);
            }
        }

        float tmax0 = -1e30f, tmax1 = -1e30f;
#pragma unroll
        for (int j = 0; j < 8; j++) {
            const int kj = t * 64 + j * 8 + (lane & 3) * 2;
            const bool k0ok = kj < 1023, k1ok = kj + 1 < 1023;
            s[j][0] += (okA && k0ok) ? slope * fabsf((float)(rA - kj))     : 0.f;
            s[j][1] += (okA && k1ok) ? slope * fabsf((float)(rA - kj - 1)) : 0.f;
            s[j][2] += (okB && k0ok) ? slope * fabsf((float)(rB - kj))     : 0.f;
            s[j][3] += (okB && k1ok) ? slope * fabsf((float)(rB - kj - 1)) : 0.f;
            tmax0 = fmaxf(tmax0, fmaxf(s[j][0], s[j][1]));
            tmax1 = fmaxf(tmax1, fmaxf(s[j][2], s[j][3]));
        }
        tmax0 = fmaxf(tmax0, __shfl_xor_sync(0xffffffffu, tmax0, 1));
        tmax0 = fmaxf(tmax0, __shfl_xor_sync(0xffffffffu, tmax0, 2));
        tmax1 = fmaxf(tmax1, __shfl_xor_sync(0xffffffffu, tmax1, 1));
        tmax1 = fmaxf(tmax1, __shfl_xor_sync(0xffffffffu, tmax1, 2));

        const float mn0 = fmaxf(m0, tmax0), mn1 = fmaxf(m1, tmax1);
        const float al0 = __expf(m0 - mn0), al1 = __expf(m1 - mn1);
        m0 = mn0; m1 = mn1;

        float rs0 = 0.f, rs1 = 0.f;
#pragma unroll
        for (int j = 0; j < 8; j++) {
            s[j][0] = __expf(s[j][0] - mn0); rs0 += s[j][0];
            s[j][1] = __expf(s[j][1] - mn0); rs0 += s[j][1];
            s[j][2] = __expf(s[j][2] - mn1); rs1 += s[j][2];
            s[j][3] = __expf(s[j][3] - mn1); rs1 += s[j][3];
        }
        rs0 += __shfl_xor_sync(0xffffffffu, rs0, 1);
        rs0 += __shfl_xor_sync(0xffffffffu, rs0, 2);
        rs1 += __shfl_xor_sync(0xffffffffu, rs1, 1);
        rs1 += __shfl_xor_sync(0xffffffffu, rs1, 2);
        l0s = l0s * al0 + rs0;
        l1s = l1s * al1 + rs1;
#pragma unroll
        for (int j = 0; j < 8; j++) {
            oacc[j][0] *= al0; oacc[j][1] *= al0;
            oacc[j][2] *= al1; oacc[j][3] *= al1;
        }

        uint32_t pfh[4][4], pfl[4][4];
#pragma unroll
        for (int kk = 0; kk < 4; kk++) {
#pragma unroll
            for (int half = 0; half < 2; half++) {
                const int j = 2 * kk + half;
                uint16_t h0, l0, h1, l1, h2, l2, h3, l3;
                split_bf(s[j][0], h0, l0); split_bf(s[j][1], h1, l1);
                split_bf(s[j][2], h2, l2); split_bf(s[j][3], h3, l3);
                pfh[kk][half*2+0] = (uint32_t)h0 | ((uint32_t)h1 << 16);
                pfh[kk][half*2+1] = (uint32_t)h2 | ((uint32_t)h3 << 16);
                pfl[kk][half*2+0] = (uint32_t)l0 | ((uint32_t)l1 << 16);
                pfl[kk][half*2+1] = (uint32_t)l2 | ((uint32_t)l3 << 16);
            }
        }

        const uint32_t vbase = vb + (uint32_t)(((lane >> 3) & 1) * 8 + (lane & 7)) * ASTR
                             + (lane >> 4) * 16;
#pragma unroll
        for (int kk = 0; kk < 4; kk++) {
#pragma unroll
            for (int nb = 0; nb < 4; nb++) {
                uint32_t v0, v1, v2, v3, w0, w1, w2, w3;
                const uint32_t ad = vbase + kk * 16 * ASTR + nb * 32;
                ldm_x4t(ad,       v0, v1, v2, v3);
                ldm_x4t(ad + ATB, w0, w1, w2, w3);
                mma_bf(oacc[nb*2],   pfh[kk], v0, v1);
                mma_bf(oacc[nb*2],   pfl[kk], v0, v1);
                mma_bf(oacc[nb*2],   pfh[kk], w0, w1);
                mma_bf(oacc[nb*2+1], pfh[kk], v2, v3);
                mma_bf(oacc[nb*2+1], pfl[kk], v2, v3);
                mma_bf(oacc[nb*2+1], pfh[kk], w2, w3);
            }
        }
    }

    const float inv0 = 1.f / l0s, inv1 = 1.f / l1s;
#pragma unroll
    for (int j = 0; j < 8; j++) {
        const int d0 = j * 8 + (lane & 3) * 2;
        uint16_t h0, l0, h1, l1;
        split_h(oacc[j][0] * inv0, h0, l0); split_h(oacc[j][1] * inv0, h1, l1);
        size_t o = ((size_t)b * 1024 + rA) * DMODEL + h * 64 + d0;
        *(uint32_t*)(out_h + o) = (uint32_t)h0 | ((uint32_t)h1 << 16);
        *(uint32_t*)(out_l + o) = (uint32_t)l0 | ((uint32_t)l1 << 16);
        split_h(oacc[j][2] * inv1, h0, l0); split_h(oacc[j][3] * inv1, h1, l1);
        o += (size_t)8 * DMODEL;
        *(uint32_t*)(out_h + o) = (uint32_t)h0 | ((uint32_t)h1 << 16);
        *(uint32_t*)(out_l + o) = (uint32_t)l0 | ((uint32_t)l1 << 16);
    }
}

// ---------------- LayerNorm ----------------
template<bool HL>
__global__ void __launch_bounds__(256) ln_kernel2(
    const float* __restrict__ x, const float* __restrict__ g,
    float* __restrict__ y,
    uint16_t* __restrict__ yh, uint16_t* __restrict__ yl)
{
    __shared__ float red[256];
    const int row = blockIdx.x;
    const int tid = threadIdx.x;
    const float* xr = x + (size_t)row * DMODEL;

    float v[4];
    float s = 0.f;
#pragma unroll
    for (int u = 0; u < 4; u++) { v[u] = xr[tid + u * 256]; s += v[u]; }
    red[tid] = s; __syncthreads();
    for (int o = 128; o; o >>= 1) {
        if (tid < o) red[tid] += red[tid + o];
        __syncthreads();
    }
    const float mu = red[0] * (1.f / 1024.f);
    __syncthreads();

    float q = 0.f;
#pragma unroll
    for (int u = 0; u < 4; u++) { const float d = v[u] - mu; q += d * d; }
    red[tid] = q; __syncthreads();
    for (int o = 128; o; o >>= 1) {
        if (tid < o) red[tid] += red[tid + o];
        __syncthreads();
    }
    const float r = rsqrtf(red[0] * (1.f / 1024.f) + 1e-5f);

#pragma unroll
    for (int u = 0; u < 4; u++) {
        const float val = (v[u] - mu) * r * g[tid + u * 256];
        const size_t o = (size_t)row * DMODEL + tid + u * 256;
        if (HL) {
            uint16_t h0, l0;
            split_h(val, h0, l0);
            yh[o] = h0;
            yl[o] = l0;
        } else {
            y[o] = val;
        }
    }
}

// ---------------- fused one-shot converter (weights + x init) ----------------
__device__ __forceinline__ uint2 h4pack(float4 v) {
    __half2 a = __floats2half2_rn(v.x, v.y);
    __half2 b = __floats2half2_rn(v.z, v.w);
    uint2 u; u.x = *(uint32_t*)&a; u.y = *(uint32_t*)&b;
    return u;
}

__global__ void __launch_bounds__(256) convert_all(
    const float4* __restrict__ x_in, float4* __restrict__ gx,
    uint2* __restrict__ xh, uint2* __restrict__ xl,
    const float4* __restrict__ qw,  uint2* __restrict__ qo,
    const float4* __restrict__ aow, uint2* __restrict__ aoo,
    const float4* __restrict__ miw, uint2* __restrict__ mio,
    const float4* __restrict__ mow, uint2* __restrict__ moo,
    const float4* __restrict__ skw, uint2* __restrict__ sko)
{
    const int stride = gridDim.x * blockDim.x;
    const int g0 = blockIdx.x * blockDim.x + threadIdx.x;

    for (int i = g0; i < TOK * DMODEL / 4; i += stride) {
        float4 v = x_in[i];
        gx[i] = v;
        uint16_t h[4], l[4];
        split_h(v.x, h[0], l[0]); split_h(v.y, h[1], l[1]);
        split_h(v.z, h[2], l[2]); split_h(v.w, h[3], l[3]);
        uint2 uh, ul;
        uh.x = (uint32_t)h[0] | ((uint32_t)h[1] << 16);
        uh.y = (uint32_t)h[2] | ((uint32_t)h[3] << 16);
        ul.x = (uint32_t)l[0] | ((uint32_t)l[1] << 16);
        ul.y = (uint32_t)l[2] | ((uint32_t)l[3] << 16);
        xh[i] = uh; xl[i] = ul;
    }
    for (int i = g0; i < NL * DQKV * DMODEL / 4; i += stride) qo[i]  = h4pack(qw[i]);
    for (int i = g0; i < NL * DMODEL * DMODEL / 4; i += stride) aoo[i] = h4pack(aow[i]);
    for (int i = g0; i < NL * DFF * DMODEL / 4; i += stride) mio[i] = h4pack(miw[i]);
    for (int i = g0; i < NL * DMODEL * DFF / 4; i += stride) moo[i] = h4pack(mow[i]);
    for (int i = g0; i < 4 * DMODEL * 2 * DMODEL / 4; i += stride) {
        float4 v = skw[i];
        if (((i * 4) & 2047) >= 1024) {   // fold 2^-0.5 into second K half
            v.x *= 0.70710678118654752440f; v.y *= 0.70710678118654752440f;
            v.z *= 0.70710678118654752440f; v.w *= 0.70710678118654752440f;
        }
        sko[i] = h4pack(v);
    }
}

// ---------------- host orchestration ----------------
extern "C" void kernel_launch(void* const* d_in, const int* in_sizes, int n_in,
                              void* d_out, int out_size)
{
    (void)in_sizes; (void)n_in; (void)out_size;
    const float* x_in       = (const float*)d_in[0];
    const float* attn_w     = (const float*)d_in[1];
    const float* attn_out_w = (const float*)d_in[2];
    const float* mlp_ln_g   = (const float*)d_in[3];
    const float* mlp_in_w   = (const float*)d_in[4];
    const float* mlp_in_b   = (const float*)d_in[5];
    const float* mlp_out_w  = (const float*)d_in[6];
    const float* mlp_out_b  = (const float*)d_in[7];
    const float* skip_w     = (const float*)d_in[8];
    const float* skip_b     = (const float*)d_in[9];
    const float* out_ln_g   = (const float*)d_in[10];

    float* gx;
    cudaGetSymbolAddress((void**)&gx, g_x);

    __half *xAh, *xAl, *xBh, *xBl, *v2h, *v2l, *v3h, *v3l, *v4h, *v4l;
    cudaGetSymbolAddress((void**)&xAh, a_xA_h); cudaGetSymbolAddress((void**)&xAl, a_xA_l);
    cudaGetSymbolAddress((void**)&xBh, a_xB_h); cudaGetSymbolAddress((void**)&xBl, a_xB_l);
    cudaGetSymbolAddress((void**)&v2h, s_v2_h); cudaGetSymbolAddress((void**)&v2l, s_v2_l);
    cudaGetSymbolAddress((void**)&v3h, s_v3_h); cudaGetSymbolAddress((void**)&v3l, s_v3_l);
    cudaGetSymbolAddress((void**)&v4h, s_v4_h); cudaGetSymbolAddress((void**)&v4l, s_v4_l);

    __nv_bfloat16 *qkvh, *qkvl;
    cudaGetSymbolAddress((void**)&qkvh, a_qkv_h); cudaGetSymbolAddress((void**)&qkvl, a_qkv_l);
    __half *ath, *atl, *lnh, *lnl, *ffh, *ffl;
    cudaGetSymbolAddress((void**)&ath, a_at_h); cudaGetSymbolAddress((void**)&atl, a_at_l);
    cudaGetSymbolAddress((void**)&lnh, a_ln_h); cudaGetSymbolAddress((void**)&lnl, a_ln_l);
    cudaGetSymbolAddress((void**)&ffh, a_ff_h); cudaGetSymbolAddress((void**)&ffl, a_ff_l);

    __half *wq, *wao, *wmi, *wmo, *wsk;
    cudaGetSymbolAddress((void**)&wq,  w_qkv);
    cudaGetSymbolAddress((void**)&wao, w_ao);
    cudaGetSymbolAddress((void**)&wmi, w_mi);
    cudaGetSymbolAddress((void**)&wmo, w_mo);
    cudaGetSymbolAddress((void**)&wsk, w_sk);

    cudaFuncSetAttribute((const void*)gemm_f16<8,  false>, cudaFuncAttributeMaxDynamicSharedMemorySize, GEMM_SMEM);
    cudaFuncSetAttribute((const void*)gemm_f16<60, false>, cudaFuncAttributeMaxDynamicSharedMemorySize, GEMM_SMEM);
    cudaFuncSetAttribute((const void*)gemm_f16<43, false>, cudaFuncAttributeMaxDynamicSharedMemorySize, GEMM_SMEM);
    cudaFuncSetAttribute((const void*)gemm_f16<61, false>, cudaFuncAttributeMaxDynamicSharedMemorySize, GEMM_SMEM);
    cudaFuncSetAttribute((const void*)gemm_f16<57, true>,  cudaFuncAttributeMaxDynamicSharedMemorySize, GEMM_SMEM);
    cudaFuncSetAttribute(attn_hmma, cudaFuncAttributeMaxDynamicSharedMemorySize, ATTN_SMEM);

    // one fused convert+init launch
    convert_all<<<1184, 256>>>(
        (const float4*)x_in, (float4*)gx, (uint2*)xAh, (uint2*)xAl,
        (const float4*)attn_w,     (uint2*)wq,
        (const float4*)attn_out_w, (uint2*)wao,
        (const float4*)mlp_in_w,   (uint2*)wmi,
        (const float4*)mlp_out_w,  (uint2*)wmo,
        (const float4*)skip_w,     (uint2*)wsk);

    const size_t HBYTES = sizeof(__half) * (size_t)TOK * DMODEL;

    __half* curh = xAh;  __half* curl = xAl;
    __half* alth = xBh;  __half* altl = xBl;

    for (int i = 0; i < NL; i++) {
        if (i >= 5) {
            __half* svh = (i == 5) ? v4h : (i == 6) ? v3h : v2h;
            __half* svl = (i == 5) ? v4l : (i == 6) ? v3l : v2l;
            const int j = i - 4;
            gemm_f16<57, true><<<dim3(DMODEL / 128, TOK / 128), 256, GEMM_SMEM>>>(
                curh, curl, svh, svl,
                wsk + (size_t)j * DMODEL * 2 * DMODEL,
                skip_b + (size_t)j * DMODEL, nullptr,
                gx, (uint16_t*)alth, (uint16_t*)altl, DMODEL, 2 * DMODEL);
            __half* th = curh; curh = alth; alth = th;
            __half* tl = curl; curl = altl; altl = tl;
        }
        // QKV -> bf16 hi/lo (attention input)
        gemm_f16<8, false><<<dim3(DQKV / 128, TOK / 128), 256, GEMM_SMEM>>>(
            curh, curl, nullptr, nullptr,
            wq + (size_t)i * DQKV * DMODEL,
            nullptr, nullptr, nullptr,
            (uint16_t*)qkvh, (uint16_t*)qkvl, DQKV, DMODEL);
        // attention -> fp16 hi/lo
        attn_hmma<<<dim3(16, 16, 2), 128, ATTN_SMEM>>>(
            qkvh, qkvl, (uint16_t*)ath, (uint16_t*)atl);
        // attn out proj + residual -> x (fp32 + fp16 hi/lo)
        gemm_f16<60, false><<<dim3(DMODEL / 128, TOK / 128), 256, GEMM_SMEM>>>(
            ath, atl, nullptr, nullptr,
            wao + (size_t)i * DMODEL * DMODEL,
            nullptr, gx, gx,
            (uint16_t*)curh, (uint16_t*)curl, DMODEL, DMODEL);
        // MLP LN -> fp16 hi/lo
        ln_kernel2<true><<<TOK, 256>>>(gx, mlp_ln_g + (size_t)i * DMODEL,
                                       nullptr, (uint16_t*)lnh, (uint16_t*)lnl);
        // MLP in + bias + gelu -> fp16 hi/lo
        gemm_f16<43, false><<<dim3(DFF / 128, TOK / 128), 256, GEMM_SMEM>>>(
            lnh, lnl, nullptr, nullptr,
            wmi + (size_t)i * DFF * DMODEL,
            mlp_in_b + (size_t)i * DFF, nullptr, nullptr,
            (uint16_t*)ffh, (uint16_t*)ffl, DFF, DMODEL);
        // MLP out + bias + residual -> x (fp32 + fp16 hi/lo)
        gemm_f16<61, false><<<dim3(DMODEL / 128, TOK / 128), 256, GEMM_SMEM>>>(
            ffh, ffl, nullptr, nullptr,
            wmo + (size_t)i * DMODEL * DFF,
            mlp_out_b + (size_t)i * DMODEL, gx, gx,
            (uint16_t*)curh, (uint16_t*)curl, DMODEL, DFF);

        if (i == 2) {
            cudaMemcpyAsync(v2h, curh, HBYTES, cudaMemcpyDeviceToDevice, 0);
            cudaMemcpyAsync(v2l, curl, HBYTES, cudaMemcpyDeviceToDevice, 0);
        }
        if (i == 3) {
            cudaMemcpyAsync(v3h, curh, HBYTES, cudaMemcpyDeviceToDevice, 0);
            cudaMemcpyAsync(v3l, curl, HBYTES, cudaMemcpyDeviceToDevice, 0);
        }
        if (i == 4) {
            cudaMemcpyAsync(v4h, curh, HBYTES, cudaMemcpyDeviceToDevice, 0);
            cudaMemcpyAsync(v4l, curl, HBYTES, cudaMemcpyDeviceToDevice, 0);
        }
    }

    ln_kernel2<false><<<TOK, 256>>>(gx, out_ln_g, (float*)d_out, nullptr, nullptr);
}

// round 7
// speedup vs baseline: 3.4011x; 1.1021x over previous
#include <cuda_runtime.h>
#include <cuda_bf16.h>
#include <cuda_fp16.h>
#include <math.h>
#include <stdint.h>

// ---------------- problem constants ----------------
#define TOK    2048
#define DMODEL 1024
#define DQKV   3072
#define DFF    4096
#define NL     8

// ---------------- scratch (device globals, no allocs) ----------------
__device__ float g_x[TOK * DMODEL];

__device__ __half a_xA_h[TOK * DMODEL];
__device__ __half a_xA_l[TOK * DMODEL];
__device__ __half a_xB_h[TOK * DMODEL];
__device__ __half a_xB_l[TOK * DMODEL];
__device__ __half s_v2_h[TOK * DMODEL];
__device__ __half s_v2_l[TOK * DMODEL];
__device__ __half s_v3_h[TOK * DMODEL];
__device__ __half s_v3_l[TOK * DMODEL];
__device__ __half s_v4_h[TOK * DMODEL];
__device__ __half s_v4_l[TOK * DMODEL];
__device__ __nv_bfloat16 a_qkv_h[TOK * DQKV];
__device__ __nv_bfloat16 a_qkv_l[TOK * DQKV];
__device__ __half a_at_h[TOK * DMODEL];
__device__ __half a_at_l[TOK * DMODEL];
__device__ __half a_ln_h[TOK * DMODEL];
__device__ __half a_ln_l[TOK * DMODEL];
__device__ __half a_ff_h[TOK * DFF];
__device__ __half a_ff_l[TOK * DFF];
__device__ __half w_qkv[NL * DQKV * DMODEL];
__device__ __half w_ao [NL * DMODEL * DMODEL];
__device__ __half w_mi [NL * DFF * DMODEL];
__device__ __half w_mo [NL * DMODEL * DFF];
__device__ __half w_sk [4 * DMODEL * 2 * DMODEL];  // cols >=1024 pre-scaled by 2^-0.5

// ---------------- helpers ----------------
__device__ __forceinline__ uint32_t smem_u32(const void* p) {
    uint32_t a;
    asm("{ .reg .u64 t; cvta.to.shared.u64 t, %1; cvt.u32.u64 %0, t; }"
        : "=r"(a) : "l"(p));
    return a;
}

__device__ __forceinline__ void cp16(uint32_t dst, const void* src) {
    asm volatile("cp.async.cg.shared.global [%0], [%1], 16;" :: "r"(dst), "l"(src));
}

__device__ __forceinline__ void ldm_x4(uint32_t addr, uint32_t& r0, uint32_t& r1,
                                       uint32_t& r2, uint32_t& r3) {
    asm volatile("ldmatrix.sync.aligned.m8n8.x4.shared.b16 {%0,%1,%2,%3}, [%4];"
                 : "=r"(r0), "=r"(r1), "=r"(r2), "=r"(r3) : "r"(addr));
}

__device__ __forceinline__ void ldm_x4t(uint32_t addr, uint32_t& r0, uint32_t& r1,
                                        uint32_t& r2, uint32_t& r3) {
    asm volatile("ldmatrix.sync.aligned.m8n8.x4.trans.shared.b16 {%0,%1,%2,%3}, [%4];"
                 : "=r"(r0), "=r"(r1), "=r"(r2), "=r"(r3) : "r"(addr));
}

__device__ __forceinline__ void mma_bf(float* c, const uint32_t* a,
                                       uint32_t b0, uint32_t b1) {
    asm volatile(
        "mma.sync.aligned.m16n8k16.row.col.f32.bf16.bf16.f32 "
        "{%0,%1,%2,%3}, {%4,%5,%6,%7}, {%8,%9}, {%0,%1,%2,%3};"
        : "+f"(c[0]), "+f"(c[1]), "+f"(c[2]), "+f"(c[3])
        : "r"(a[0]), "r"(a[1]), "r"(a[2]), "r"(a[3]), "r"(b0), "r"(b1));
}

__device__ __forceinline__ void mma_fp(float* c, const uint32_t* a,
                                       uint32_t b0, uint32_t b1) {
    asm volatile(
        "mma.sync.aligned.m16n8k16.row.col.f32.f16.f16.f32 "
        "{%0,%1,%2,%3}, {%4,%5,%6,%7}, {%8,%9}, {%0,%1,%2,%3};"
        : "+f"(c[0]), "+f"(c[1]), "+f"(c[2]), "+f"(c[3])
        : "r"(a[0]), "r"(a[1]), "r"(a[2]), "r"(a[3]), "r"(b0), "r"(b1));
}

__device__ __forceinline__ void split_bf(float v, uint16_t& h, uint16_t& l) {
    __nv_bfloat16 hb = __float2bfloat16_rn(v);
    __nv_bfloat16 lb = __float2bfloat16_rn(v - __bfloat162float(hb));
    h = *(uint16_t*)&hb;
    l = *(uint16_t*)&lb;
}

__device__ __forceinline__ void split_h(float v, uint16_t& h, uint16_t& l) {
    __half hb = __float2half_rn(v);
    __half lb = __float2half_rn(v - __half2float(hb));
    h = *(uint16_t*)&hb;
    l = *(uint16_t*)&lb;
}

// ---------------- fp16 2-term HMMA GEMM (templated tile) ----------------
// C = act(A * W^T + bias)(+res); A = Ah+Al fp16 pair, W single fp16.
// FM = A-fragments per warp (M per CTA = FM*32). FM=4 -> 128xN128, FM=2 -> 64xN128.
// FLAGS: 1=bias, 2=gelu, 4=residual, 8=write hi/lo, 16=write fp32, 32=hi/lo fp16
#define GBK   32
#define GROWB 80

template<int FLAGS, bool SPLITA, int FM, int NST>
__global__ void __launch_bounds__(256, 2) gemm_f16(
    const __half* __restrict__ Ah, const __half* __restrict__ Al,
    const __half* __restrict__ A2h, const __half* __restrict__ A2l,
    const __half* __restrict__ W,
    const float* __restrict__ bias, const float* __restrict__ res,
    float* __restrict__ C, uint16_t* __restrict__ Cbh,
    uint16_t* __restrict__ Cbl, int N, int K)
{
    constexpr int BM     = FM * 32;
    constexpr int ATILEB = BM * GROWB;
    constexpr int WTILEB = 128 * GROWB;
    constexpr int STRIDE = 2 * ATILEB + WTILEB;

    extern __shared__ char smem[];
    const uint32_t sb = smem_u32(smem);
    const int tid  = threadIdx.x;
    const int wid  = tid >> 5;
    const int lane = tid & 31;
    const int wm   = wid >> 2;          // 0..1
    const int wn   = wid & 3;           // 0..3
    const int bm   = blockIdx.y * BM;
    const int bn   = blockIdx.x * 128;

    // per-thread A load mapping
    const int a_r = (FM == 4) ? (tid >> 1) : (tid >> 2);
    const int a_c = (FM == 4) ? ((tid & 1) * 16) : ((tid & 3) * 8);   // halfs
    const uint32_t sA = (uint32_t)a_r * GROWB + a_c * 2;
    const size_t a_goffK = (size_t)(bm + a_r) * K + a_c;
    const size_t a_goff1 = (size_t)(bm + a_r) * 1024 + a_c;
    // W load mapping (2 chunks/thread)
    const int w_r = tid >> 1;
    const int w_c = (tid & 1) * 16;
    const uint32_t sW = (uint32_t)w_r * GROWB + w_c * 2;
    const size_t w_goff = (size_t)(bn + w_r) * K + w_c;

    auto load_stage = [&](int s) {
        const uint32_t base = sb + (uint32_t)(s % NST) * STRIDE;
        const size_t ko = (size_t)s * GBK;
        const __half *pah, *pal;
        if (SPLITA) {
            if (ko >= 1024) { pah = A2h + a_goff1 + (ko - 1024); pal = A2l + a_goff1 + (ko - 1024); }
            else            { pah = Ah  + a_goff1 + ko;          pal = Al  + a_goff1 + ko; }
        } else {
            pah = Ah + a_goffK + ko; pal = Al + a_goffK + ko;
        }
        if (FM == 4) {
            cp16(base + sA,               pah);
            cp16(base + sA + 16,          pah + 8);
            cp16(base + ATILEB + sA,      pal);
            cp16(base + ATILEB + sA + 16, pal + 8);
        } else {
            cp16(base + sA,          pah);
            cp16(base + ATILEB + sA, pal);
        }
        const __half* pw = W + w_goff + ko;
        cp16(base + 2 * ATILEB + sW,      pw);
        cp16(base + 2 * ATILEB + sW + 16, pw + 8);
        asm volatile("cp.async.commit_group;");
    };

    const int S = K / GBK;
    for (int s = 0; s < NST - 1; s++) load_stage(s);

    float acc[FM][4][4];
#pragma unroll
    for (int i = 0; i < FM; i++)
#pragma unroll
        for (int j = 0; j < 4; j++)
#pragma unroll
            for (int k = 0; k < 4; k++) acc[i][j][k] = 0.f;

    const uint32_t aoff = (uint32_t)(wm * (FM * 16) + (lane & 15)) * GROWB
                        + (lane >> 4) * 16;
    const uint32_t boff = (uint32_t)(wn * 32 + (lane & 7) + ((lane >> 4) & 1) * 8) * GROWB
                        + ((lane >> 3) & 1) * 16 + 2 * ATILEB;

    for (int s = 0; s < S; s++) {
        asm volatile("cp.async.wait_group %0;" :: "n"(NST - 2) : "memory");
        __syncthreads();

        const int pf = s + NST - 1;
        if (pf < S) load_stage(pf);
        else        asm volatile("cp.async.commit_group;");

        const uint32_t base = sb + (uint32_t)(s % NST) * STRIDE;
#pragma unroll
        for (int k16 = 0; k16 < 2; k16++) {
            uint32_t ah[FM][4], al[FM][4], bb[2][4];
#pragma unroll
            for (int fm = 0; fm < FM; fm++) {
                const uint32_t ao = base + aoff + fm * 16 * GROWB + k16 * 32;
                ldm_x4(ao,          ah[fm][0], ah[fm][1], ah[fm][2], ah[fm][3]);
                ldm_x4(ao + ATILEB, al[fm][0], al[fm][1], al[fm][2], al[fm][3]);
            }
#pragma unroll
            for (int fnp = 0; fnp < 2; fnp++) {
                const uint32_t bo = base + boff + fnp * 16 * GROWB + k16 * 32;
                ldm_x4(bo, bb[fnp][0], bb[fnp][1], bb[fnp][2], bb[fnp][3]);
            }
#pragma unroll
            for (int fm = 0; fm < FM; fm++) {
#pragma unroll
                for (int fnp = 0; fnp < 2; fnp++) {
                    float* c0 = acc[fm][fnp * 2 + 0];
                    float* c1 = acc[fm][fnp * 2 + 1];
                    mma_fp(c0, ah[fm], bb[fnp][0], bb[fnp][1]);
                    mma_fp(c0, al[fm], bb[fnp][0], bb[fnp][1]);
                    mma_fp(c1, ah[fm], bb[fnp][2], bb[fnp][3]);
                    mma_fp(c1, al[fm], bb[fnp][2], bb[fnp][3]);
                }
            }
        }
    }

    // ---- epilogue ----
#pragma unroll
    for (int fm = 0; fm < FM; fm++) {
#pragma unroll
        for (int fn = 0; fn < 4; fn++) {
            const int r0 = bm + wm * (FM * 16) + fm * 16 + (lane >> 2);
            const int c0 = bn + wn * 32 + fn * 8 + (lane & 3) * 2;
            float v[4] = { acc[fm][fn][0], acc[fm][fn][1],
                           acc[fm][fn][2], acc[fm][fn][3] };
            if (FLAGS & 1) {
                const float b0 = __ldg(bias + c0), b1 = __ldg(bias + c0 + 1);
                v[0] += b0; v[1] += b1; v[2] += b0; v[3] += b1;
            }
            if (FLAGS & 2) {
#pragma unroll
                for (int u = 0; u < 4; u++)
                    v[u] = 0.5f * v[u] * (1.f + erff(v[u] * 0.7071067811865476f));
            }
            if (FLAGS & 4) {
                const float2 ra = *(const float2*)(res + (size_t)r0 * N + c0);
                const float2 rb = *(const float2*)(res + (size_t)(r0 + 8) * N + c0);
                v[0] += ra.x; v[1] += ra.y; v[2] += rb.x; v[3] += rb.y;
            }
            if (FLAGS & 16) {
                float2 oa; oa.x = v[0]; oa.y = v[1];
                float2 ob; ob.x = v[2]; ob.y = v[3];
                *(float2*)(C + (size_t)r0 * N + c0) = oa;
                *(float2*)(C + (size_t)(r0 + 8) * N + c0) = ob;
            }
            if (FLAGS & 8) {
                uint16_t h0, l0, h1, l1;
#pragma unroll
                for (int hf = 0; hf < 2; hf++) {
                    const int rr = r0 + hf * 8;
                    const float va = v[hf * 2 + 0], vb2 = v[hf * 2 + 1];
                    if (FLAGS & 32) { split_h(va, h0, l0);  split_h(vb2, h1, l1); }
                    else            { split_bf(va, h0, l0); split_bf(vb2, h1, l1); }
                    *(uint32_t*)(Cbh + (size_t)rr * N + c0) = (uint32_t)h0 | ((uint32_t)h1 << 16);
                    *(uint32_t*)(Cbl + (size_t)rr * N + c0) = (uint32_t)l0 | ((uint32_t)l1 << 16);
                }
            }
        }
    }
}

// GEMM smem sizes
#define GSMEM_FM4 ((2 * 128 * GROWB + 128 * GROWB) * 3)   // 92160
#define GSMEM_FM2 ((2 * 64 * GROWB + 128 * GROWB) * 4)    // 81920

// ---------------- HMMA flash attention (bf16x3 inside, fp16 hi/lo out) ------
#define ASTR 144
#define ATB  (64 * ASTR)
#define ATTN_SMEM (10 * ATB)

__global__ void __launch_bounds__(128) attn_hmma(
    const __nv_bfloat16* __restrict__ qh, const __nv_bfloat16* __restrict__ ql,
    uint16_t* __restrict__ out_h, uint16_t* __restrict__ out_l)
{
    extern __shared__ char smc[];
    const uint32_t sb = smem_u32(smc);
    const int b = blockIdx.z, h = blockIdx.y, q0 = blockIdx.x * 64;
    const int tid = threadIdx.x, wid = tid >> 5, lane = tid & 31;
    const float slope = -exp2f(-0.5f * (float)(h + 1));
    const size_t base = (size_t)b * 1024 * DQKV + (size_t)h * 64;

    {
        const int which = tid >> 6, r = tid & 63;
        const __nv_bfloat16* src = (which ? ql : qh) + base + (size_t)(q0 + r) * DQKV;
        const uint32_t dst = sb + which * ATB + r * ASTR;
#pragma unroll
        for (int c = 0; c < 8; c++) cp16(dst + c * 16, src + c * 8);
        asm volatile("cp.async.commit_group;");
    }

    auto load_kv = [&](int t) {
        const uint32_t bufb = sb + 2 * ATB + (t & 1) * (4 * ATB) + wid * ATB;
        const __nv_bfloat16* sp = ((wid & 1) ? ql : qh) + base + ((wid < 2) ? 1024 : 2048);
#pragma unroll
        for (int rr = 0; rr < 2; rr++) {
            const int r = lane + rr * 32;
            const __nv_bfloat16* src = sp + (size_t)(t * 64 + r) * DQKV;
            const uint32_t dst = bufb + r * ASTR;
#pragma unroll
            for (int c = 0; c < 8; c++) cp16(dst + c * 16, src + c * 8);
        }
        asm volatile("cp.async.commit_group;");
    };

    load_kv(0);
    asm volatile("cp.async.wait_group 0;" ::: "memory");
    __syncthreads();

    uint32_t qfh[4][4], qfl[4][4];
    {
        const uint32_t ao = sb + (uint32_t)(wid * 16 + (lane & 15)) * ASTR + (lane >> 4) * 16;
#pragma unroll
        for (int kk = 0; kk < 4; kk++) {
            ldm_x4(ao + kk * 32,       qfh[kk][0], qfh[kk][1], qfh[kk][2], qfh[kk][3]);
            ldm_x4(ao + ATB + kk * 32, qfl[kk][0], qfl[kk][1], qfl[kk][2], qfl[kk][3]);
        }
        const __nv_bfloat162 sc = __float2bfloat162_rn(0.125f);
#pragma unroll
        for (int kk = 0; kk < 4; kk++)
#pragma unroll
            for (int u = 0; u < 4; u++) {
                __nv_bfloat162 vh = *(__nv_bfloat162*)&qfh[kk][u];
                __nv_bfloat162 vl = *(__nv_bfloat162*)&qfl[kk][u];
                vh = __hmul2(vh, sc); vl = __hmul2(vl, sc);
                qfh[kk][u] = *(uint32_t*)&vh; qfl[kk][u] = *(uint32_t*)&vl;
            }
    }

    const int rA = q0 + wid * 16 + (lane >> 2);
    const int rB = rA + 8;
    const bool okA = rA < 1023, okB = rB < 1023;

    float m0 = -1e30f, m1 = -1e30f, l0s = 0.f, l1s = 0.f;
    float oacc[8][4];
#pragma unroll
    for (int j = 0; j < 8; j++)
#pragma unroll
        for (int u = 0; u < 4; u++) oacc[j][u] = 0.f;

    for (int t = 0; t < 16; t++) {
        if (t > 0) {
            asm volatile("cp.async.wait_group 0;" ::: "memory");
            __syncthreads();
        }
        if (t < 15) load_kv(t + 1);

        const uint32_t kb = sb + 2 * ATB + (t & 1) * (4 * ATB);
        const uint32_t vb = kb + 2 * ATB;

        float s[8][4];
#pragma unroll
        for (int j = 0; j < 8; j++)
#pragma unroll
            for (int u = 0; u < 4; u++) s[j][u] = 0.f;

        const uint32_t bbase = kb + (uint32_t)((lane & 7) + ((lane >> 4) & 1) * 8) * ASTR
                             + ((lane >> 3) & 1) * 16;
#pragma unroll
        for (int kk = 0; kk < 4; kk++) {
#pragma unroll
            for (int nb = 0; nb < 4; nb++) {
                uint32_t b0, b1, b2, b3, c0, c1, c2, c3;
                const uint32_t ad = bbase + nb * 16 * ASTR + kk * 32;
                ldm_x4(ad,       b0, b1, b2, b3);
                ldm_x4(ad + ATB, c0, c1, c2, c3);
                mma_bf(s[nb*2],   qfh[kk], b0, b1);
                mma_bf(s[nb*2],   qfl[kk], b0, b1);
                mma_bf(s[nb*2],   qfh[kk], c0, c1);
                mma_bf(s[nb*2+1], qfh[kk], b2, b3);
                mma_bf(s[nb*2+1], qfl[kk], b2, b3);
                mma_bf(s[nb*2+1], qfh[kk], c2, c3);
            }
        }

        float tmax0 = -1e30f, tmax1 = -1e30f;
#pragma unroll
        for (int j = 0; j < 8; j++) {
            const int kj = t * 64 + j * 8 + (lane & 3) * 2;
            const bool k0ok = kj < 1023, k1ok = kj + 1 < 1023;
            s[j][0] += (okA && k0ok) ? slope * fabsf((float)(rA - kj))     : 0.f;
            s[j][1] += (okA && k1ok) ? slope * fabsf((float)(rA - kj - 1)) : 0.f;
            s[j][2] += (okB && k0ok) ? slope * fabsf((float)(rB - kj))     : 0.f;
            s[j][3] += (okB && k1ok) ? slope * fabsf((float)(rB - kj - 1)) : 0.f;
            tmax0 = fmaxf(tmax0, fmaxf(s[j][0], s[j][1]));
            tmax1 = fmaxf(tmax1, fmaxf(s[j][2], s[j][3]));
        }
        tmax0 = fmaxf(tmax0, __shfl_xor_sync(0xffffffffu, tmax0, 1));
        tmax0 = fmaxf(tmax0, __shfl_xor_sync(0xffffffffu, tmax0, 2));
        tmax1 = fmaxf(tmax1, __shfl_xor_sync(0xffffffffu, tmax1, 1));
        tmax1 = fmaxf(tmax1, __shfl_xor_sync(0xffffffffu, tmax1, 2));

        const float mn0 = fmaxf(m0, tmax0), mn1 = fmaxf(m1, tmax1);
        const float al0 = __expf(m0 - mn0), al1 = __expf(m1 - mn1);
        m0 = mn0; m1 = mn1;

        float rs0 = 0.f, rs1 = 0.f;
#pragma unroll
        for (int j = 0; j < 8; j++) {
            s[j][0] = __expf(s[j][0] - mn0); rs0 += s[j][0];
            s[j][1] = __expf(s[j][1] - mn0); rs0 += s[j][1];
            s[j][2] = __expf(s[j][2] - mn1); rs1 += s[j][2];
            s[j][3] = __expf(s[j][3] - mn1); rs1 += s[j][3];
        }
        rs0 += __shfl_xor_sync(0xffffffffu, rs0, 1);
        rs0 += __shfl_xor_sync(0xffffffffu, rs0, 2);
        rs1 += __shfl_xor_sync(0xffffffffu, rs1, 1);
        rs1 += __shfl_xor_sync(0xffffffffu, rs1, 2);
        l0s = l0s * al0 + rs0;
        l1s = l1s * al1 + rs1;
#pragma unroll
        for (int j = 0; j < 8; j++) {
            oacc[j][0] *= al0; oacc[j][1] *= al0;
            oacc[j][2] *= al1; oacc[j][3] *= al1;
        }

        uint32_t pfh[4][4], pfl[4][4];
#pragma unroll
        for (int kk = 0; kk < 4; kk++) {
#pragma unroll
            for (int half = 0; half < 2; half++) {
                const int j = 2 * kk + half;
                uint16_t h0, l0, h1, l1, h2, l2, h3, l3;
                split_bf(s[j][0], h0, l0); split_bf(s[j][1], h1, l1);
                split_bf(s[j][2], h2, l2); split_bf(s[j][3], h3, l3);
                pfh[kk][half*2+0] = (uint32_t)h0 | ((uint32_t)h1 << 16);
                pfh[kk][half*2+1] = (uint32_t)h2 | ((uint32_t)h3 << 16);
                pfl[kk][half*2+0] = (uint32_t)l0 | ((uint32_t)l1 << 16);
                pfl[kk][half*2+1] = (uint32_t)l2 | ((uint32_t)l3 << 16);
            }
        }

        const uint32_t vbase = vb + (uint32_t)(((lane >> 3) & 1) * 8 + (lane & 7)) * ASTR
                             + (lane >> 4) * 16;
#pragma unroll
        for (int kk = 0; kk < 4; kk++) {
#pragma unroll
            for (int nb = 0; nb < 4; nb++) {
                uint32_t v0, v1, v2, v3, w0, w1, w2, w3;
                const uint32_t ad = vbase + kk * 16 * ASTR + nb * 32;
                ldm_x4t(ad,       v0, v1, v2, v3);
                ldm_x4t(ad + ATB, w0, w1, w2, w3);
                mma_bf(oacc[nb*2],   pfh[kk], v0, v1);
                mma_bf(oacc[nb*2],   pfl[kk], v0, v1);
                mma_bf(oacc[nb*2],   pfh[kk], w0, w1);
                mma_bf(oacc[nb*2+1], pfh[kk], v2, v3);
                mma_bf(oacc[nb*2+1], pfl[kk], v2, v3);
                mma_bf(oacc[nb*2+1], pfh[kk], w2, w3);
            }
        }
    }

    const float inv0 = 1.f / l0s, inv1 = 1.f / l1s;
#pragma unroll
    for (int j = 0; j < 8; j++) {
        const int d0 = j * 8 + (lane & 3) * 2;
        uint16_t h0, l0, h1, l1;
        split_h(oacc[j][0] * inv0, h0, l0); split_h(oacc[j][1] * inv0, h1, l1);
        size_t o = ((size_t)b * 1024 + rA) * DMODEL + h * 64 + d0;
        *(uint32_t*)(out_h + o) = (uint32_t)h0 | ((uint32_t)h1 << 16);
        *(uint32_t*)(out_l + o) = (uint32_t)l0 | ((uint32_t)l1 << 16);
        split_h(oacc[j][2] * inv1, h0, l0); split_h(oacc[j][3] * inv1, h1, l1);
        o += (size_t)8 * DMODEL;
        *(uint32_t*)(out_h + o) = (uint32_t)h0 | ((uint32_t)h1 << 16);
        *(uint32_t*)(out_l + o) = (uint32_t)l0 | ((uint32_t)l1 << 16);
    }
}

// ---------------- LayerNorm ----------------
template<bool HL>
__global__ void __launch_bounds__(256) ln_kernel2(
    const float* __restrict__ x, const float* __restrict__ g,
    float* __restrict__ y,
    uint16_t* __restrict__ yh, uint16_t* __restrict__ yl)
{
    __shared__ float red[256];
    const int row = blockIdx.x;
    const int tid = threadIdx.x;
    const float* xr = x + (size_t)row * DMODEL;

    float v[4];
    float s = 0.f;
#pragma unroll
    for (int u = 0; u < 4; u++) { v[u] = xr[tid + u * 256]; s += v[u]; }
    red[tid] = s; __syncthreads();
    for (int o = 128; o; o >>= 1) {
        if (tid < o) red[tid] += red[tid + o];
        __syncthreads();
    }
    const float mu = red[0] * (1.f / 1024.f);
    __syncthreads();

    float q = 0.f;
#pragma unroll
    for (int u = 0; u < 4; u++) { const float d = v[u] - mu; q += d * d; }
    red[tid] = q; __syncthreads();
    for (int o = 128; o; o >>= 1) {
        if (tid < o) red[tid] += red[tid + o];
        __syncthreads();
    }
    const float r = rsqrtf(red[0] * (1.f / 1024.f) + 1e-5f);

#pragma unroll
    for (int u = 0; u < 4; u++) {
        const float val = (v[u] - mu) * r * g[tid + u * 256];
        const size_t o = (size_t)row * DMODEL + tid + u * 256;
        if (HL) {
            uint16_t h0, l0;
            split_h(val, h0, l0);
            yh[o] = h0;
            yl[o] = l0;
        } else {
            y[o] = val;
        }
    }
}

// ---------------- fused one-shot converter ----------------
__device__ __forceinline__ uint2 h4pack(float4 v) {
    __half2 a = __floats2half2_rn(v.x, v.y);
    __half2 b = __floats2half2_rn(v.z, v.w);
    uint2 u; u.x = *(uint32_t*)&a; u.y = *(uint32_t*)&b;
    return u;
}

__global__ void __launch_bounds__(256) convert_all(
    const float4* __restrict__ x_in, float4* __restrict__ gx,
    uint2* __restrict__ xh, uint2* __restrict__ xl,
    const float4* __restrict__ qw,  uint2* __restrict__ qo,
    const float4* __restrict__ aow, uint2* __restrict__ aoo,
    const float4* __restrict__ miw, uint2* __restrict__ mio,
    const float4* __restrict__ mow, uint2* __restrict__ moo,
    const float4* __restrict__ skw, uint2* __restrict__ sko)
{
    const int stride = gridDim.x * blockDim.x;
    const int g0 = blockIdx.x * blockDim.x + threadIdx.x;

    for (int i = g0; i < TOK * DMODEL / 4; i += stride) {
        float4 v = x_in[i];
        gx[i] = v;
        uint16_t h[4], l[4];
        split_h(v.x, h[0], l[0]); split_h(v.y, h[1], l[1]);
        split_h(v.z, h[2], l[2]); split_h(v.w, h[3], l[3]);
        uint2 uh, ul;
        uh.x = (uint32_t)h[0] | ((uint32_t)h[1] << 16);
        uh.y = (uint32_t)h[2] | ((uint32_t)h[3] << 16);
        ul.x = (uint32_t)l[0] | ((uint32_t)l[1] << 16);
        ul.y = (uint32_t)l[2] | ((uint32_t)l[3] << 16);
        xh[i] = uh; xl[i] = ul;
    }
    for (int i = g0; i < NL * DQKV * DMODEL / 4; i += stride) qo[i]  = h4pack(qw[i]);
    for (int i = g0; i < NL * DMODEL * DMODEL / 4; i += stride) aoo[i] = h4pack(aow[i]);
    for (int i = g0; i < NL * DFF * DMODEL / 4; i += stride) mio[i] = h4pack(miw[i]);
    for (int i = g0; i < NL * DMODEL * DFF / 4; i += stride) moo[i] = h4pack(mow[i]);
    for (int i = g0; i < 4 * DMODEL * 2 * DMODEL / 4; i += stride) {
        float4 v = skw[i];
        if (((i * 4) & 2047) >= 1024) {
            v.x *= 0.70710678118654752440f; v.y *= 0.70710678118654752440f;
            v.z *= 0.70710678118654752440f; v.w *= 0.70710678118654752440f;
        }
        sko[i] = h4pack(v);
    }
}

// ---------------- host orchestration ----------------
extern "C" void kernel_launch(void* const* d_in, const int* in_sizes, int n_in,
                              void* d_out, int out_size)
{
    (void)in_sizes; (void)n_in; (void)out_size;
    const float* x_in       = (const float*)d_in[0];
    const float* attn_w     = (const float*)d_in[1];
    const float* attn_out_w = (const float*)d_in[2];
    const float* mlp_ln_g   = (const float*)d_in[3];
    const float* mlp_in_w   = (const float*)d_in[4];
    const float* mlp_in_b   = (const float*)d_in[5];
    const float* mlp_out_w  = (const float*)d_in[6];
    const float* mlp_out_b  = (const float*)d_in[7];
    const float* skip_w     = (const float*)d_in[8];
    const float* skip_b     = (const float*)d_in[9];
    const float* out_ln_g   = (const float*)d_in[10];

    float* gx;
    cudaGetSymbolAddress((void**)&gx, g_x);

    __half *xAh, *xAl, *xBh, *xBl, *v2h, *v2l, *v3h, *v3l, *v4h, *v4l;
    cudaGetSymbolAddress((void**)&xAh, a_xA_h); cudaGetSymbolAddress((void**)&xAl, a_xA_l);
    cudaGetSymbolAddress((void**)&xBh, a_xB_h); cudaGetSymbolAddress((void**)&xBl, a_xB_l);
    cudaGetSymbolAddress((void**)&v2h, s_v2_h); cudaGetSymbolAddress((void**)&v2l, s_v2_l);
    cudaGetSymbolAddress((void**)&v3h, s_v3_h); cudaGetSymbolAddress((void**)&v3l, s_v3_l);
    cudaGetSymbolAddress((void**)&v4h, s_v4_h); cudaGetSymbolAddress((void**)&v4l, s_v4_l);

    __nv_bfloat16 *qkvh, *qkvl;
    cudaGetSymbolAddress((void**)&qkvh, a_qkv_h); cudaGetSymbolAddress((void**)&qkvl, a_qkv_l);
    __half *ath, *atl, *lnh, *lnl, *ffh, *ffl;
    cudaGetSymbolAddress((void**)&ath, a_at_h); cudaGetSymbolAddress((void**)&atl, a_at_l);
    cudaGetSymbolAddress((void**)&lnh, a_ln_h); cudaGetSymbolAddress((void**)&lnl, a_ln_l);
    cudaGetSymbolAddress((void**)&ffh, a_ff_h); cudaGetSymbolAddress((void**)&ffl, a_ff_l);

    __half *wq, *wao, *wmi, *wmo, *wsk;
    cudaGetSymbolAddress((void**)&wq,  w_qkv);
    cudaGetSymbolAddress((void**)&wao, w_ao);
    cudaGetSymbolAddress((void**)&wmi, w_mi);
    cudaGetSymbolAddress((void**)&wmo, w_mo);
    cudaGetSymbolAddress((void**)&wsk, w_sk);

    cudaFuncSetAttribute((const void*)gemm_f16<8,  false, 4, 3>, cudaFuncAttributeMaxDynamicSharedMemorySize, GSMEM_FM4);
    cudaFuncSetAttribute((const void*)gemm_f16<43, false, 4, 3>, cudaFuncAttributeMaxDynamicSharedMemorySize, GSMEM_FM4);
    cudaFuncSetAttribute((const void*)gemm_f16<60, false, 2, 4>, cudaFuncAttributeMaxDynamicSharedMemorySize, GSMEM_FM2);
    cudaFuncSetAttribute((const void*)gemm_f16<61, false, 2, 4>, cudaFuncAttributeMaxDynamicSharedMemorySize, GSMEM_FM2);
    cudaFuncSetAttribute((const void*)gemm_f16<57, true,  2, 4>, cudaFuncAttributeMaxDynamicSharedMemorySize, GSMEM_FM2);
    cudaFuncSetAttribute(attn_hmma, cudaFuncAttributeMaxDynamicSharedMemorySize, ATTN_SMEM);

    convert_all<<<1184, 256>>>(
        (const float4*)x_in, (float4*)gx, (uint2*)xAh, (uint2*)xAl,
        (const float4*)attn_w,     (uint2*)wq,
        (const float4*)attn_out_w, (uint2*)wao,
        (const float4*)mlp_in_w,   (uint2*)wmi,
        (const float4*)mlp_out_w,  (uint2*)wmo,
        (const float4*)skip_w,     (uint2*)wsk);

    const size_t HBYTES = sizeof(__half) * (size_t)TOK * DMODEL;

    __half* curh = xAh;  __half* curl = xAl;
    __half* alth = xBh;  __half* altl = xBl;

    for (int i = 0; i < NL; i++) {
        if (i >= 5) {
            __half* svh = (i == 5) ? v4h : (i == 6) ? v3h : v2h;
            __half* svl = (i == 5) ? v4l : (i == 6) ? v3l : v2l;
            const int j = i - 4;
            gemm_f16<57, true, 2, 4><<<dim3(DMODEL / 128, TOK / 64), 256, GSMEM_FM2>>>(
                curh, curl, svh, svl,
                wsk + (size_t)j * DMODEL * 2 * DMODEL,
                skip_b + (size_t)j * DMODEL, nullptr,
                gx, (uint16_t*)alth, (uint16_t*)altl, DMODEL, 2 * DMODEL);
            __half* th = curh; curh = alth; alth = th;
            __half* tl = curl; curl = altl; altl = tl;
        }
        // QKV -> bf16 hi/lo
        gemm_f16<8, false, 4, 3><<<dim3(DQKV / 128, TOK / 128), 256, GSMEM_FM4>>>(
            curh, curl, nullptr, nullptr,
            wq + (size_t)i * DQKV * DMODEL,
            nullptr, nullptr, nullptr,
            (uint16_t*)qkvh, (uint16_t*)qkvl, DQKV, DMODEL);
        // attention -> fp16 hi/lo
        attn_hmma<<<dim3(16, 16, 2), 128, ATTN_SMEM>>>(
            qkvh, qkvl, (uint16_t*)ath, (uint16_t*)atl);
        // attn out proj + residual -> x
        gemm_f16<60, false, 2, 4><<<dim3(DMODEL / 128, TOK / 64), 256, GSMEM_FM2>>>(
            ath, atl, nullptr, nullptr,
            wao + (size_t)i * DMODEL * DMODEL,
            nullptr, gx, gx,
            (uint16_t*)curh, (uint16_t*)curl, DMODEL, DMODEL);
        // MLP LN -> fp16 hi/lo
        ln_kernel2<true><<<TOK, 256>>>(gx, mlp_ln_g + (size_t)i * DMODEL,
                                       nullptr, (uint16_t*)lnh, (uint16_t*)lnl);
        // MLP in + bias + gelu
        gemm_f16<43, false, 4, 3><<<dim3(DFF / 128, TOK / 128), 256, GSMEM_FM4>>>(
            lnh, lnl, nullptr, nullptr,
            wmi + (size_t)i * DFF * DMODEL,
            mlp_in_b + (size_t)i * DFF, nullptr, nullptr,
            (uint16_t*)ffh, (uint16_t*)ffl, DFF, DMODEL);
        // MLP out + bias + residual -> x
        gemm_f16<61, false, 2, 4><<<dim3(DMODEL / 128, TOK / 64), 256, GSMEM_FM2>>>(
            ffh, ffl, nullptr, nullptr,
            wmo + (size_t)i * DMODEL * DFF,
            mlp_out_b + (size_t)i * DMODEL, gx, gx,
            (uint16_t*)curh, (uint16_t*)curl, DMODEL, DFF);

        if (i == 2) {
            cudaMemcpyAsync(v2h, curh, HBYTES, cudaMemcpyDeviceToDevice, 0);
            cudaMemcpyAsync(v2l, curl, HBYTES, cudaMemcpyDeviceToDevice, 0);
        }
        if (i == 3) {
            cudaMemcpyAsync(v3h, curh, HBYTES, cudaMemcpyDeviceToDevice, 0);
            cudaMemcpyAsync(v3l, curl, HBYTES, cudaMemcpyDeviceToDevice, 0);
        }
        if (i == 4) {
            cudaMemcpyAsync(v4h, curh, HBYTES, cudaMemcpyDeviceToDevice, 0);
            cudaMemcpyAsync(v4l, curl, HBYTES, cudaMemcpyDeviceToDevice, 0);
        }
    }

    ln_kernel2<false><<<TOK, 256>>>(gx, out_ln_g, (float*)d_out, nullptr, nullptr);
}

// round 8
// speedup vs baseline: 4.6084x; 1.3550x over previous
#include <cuda_runtime.h>
#include <cuda_bf16.h>
#include <cuda_fp16.h>
#include <math.h>
#include <stdint.h>

// ---------------- problem constants ----------------
#define TOK    2048
#define DMODEL 1024
#define DQKV   3072
#define DFF    4096
#define NL     8

// ---------------- scratch (device globals, no allocs) ----------------
__device__ float g_x[TOK * DMODEL];

__device__ __half a_xA[TOK * DMODEL];
__device__ __half a_xB[TOK * DMODEL];
__device__ __half s_v2[TOK * DMODEL];
__device__ __half s_v3[TOK * DMODEL];
__device__ __half s_v4[TOK * DMODEL];
__device__ __nv_bfloat16 a_qkv_h[TOK * DQKV];   // attention input (bf16 hi/lo, 3-term)
__device__ __nv_bfloat16 a_qkv_l[TOK * DQKV];
__device__ __half a_at[TOK * DMODEL];
__device__ __half a_ln[TOK * DMODEL];
__device__ __half a_ff[TOK * DFF];
__device__ __half w_qkv[NL * DQKV * DMODEL];
__device__ __half w_ao [NL * DMODEL * DMODEL];
__device__ __half w_mi [NL * DFF * DMODEL];
__device__ __half w_mo [NL * DMODEL * DFF];
__device__ __half w_sk [4 * DMODEL * 2 * DMODEL];  // cols >=1024 pre-scaled by 2^-0.5

// ---------------- helpers ----------------
__device__ __forceinline__ uint32_t smem_u32(const void* p) {
    uint32_t a;
    asm("{ .reg .u64 t; cvta.to.shared.u64 t, %1; cvt.u32.u64 %0, t; }"
        : "=r"(a) : "l"(p));
    return a;
}

__device__ __forceinline__ void cp16(uint32_t dst, const void* src) {
    asm volatile("cp.async.cg.shared.global [%0], [%1], 16;" :: "r"(dst), "l"(src));
}

__device__ __forceinline__ void ldm_x4(uint32_t addr, uint32_t& r0, uint32_t& r1,
                                       uint32_t& r2, uint32_t& r3) {
    asm volatile("ldmatrix.sync.aligned.m8n8.x4.shared.b16 {%0,%1,%2,%3}, [%4];"
                 : "=r"(r0), "=r"(r1), "=r"(r2), "=r"(r3) : "r"(addr));
}

__device__ __forceinline__ void ldm_x4t(uint32_t addr, uint32_t& r0, uint32_t& r1,
                                        uint32_t& r2, uint32_t& r3) {
    asm volatile("ldmatrix.sync.aligned.m8n8.x4.trans.shared.b16 {%0,%1,%2,%3}, [%4];"
                 : "=r"(r0), "=r"(r1), "=r"(r2), "=r"(r3) : "r"(addr));
}

__device__ __forceinline__ void mma_bf(float* c, const uint32_t* a,
                                       uint32_t b0, uint32_t b1) {
    asm volatile(
        "mma.sync.aligned.m16n8k16.row.col.f32.bf16.bf16.f32 "
        "{%0,%1,%2,%3}, {%4,%5,%6,%7}, {%8,%9}, {%0,%1,%2,%3};"
        : "+f"(c[0]), "+f"(c[1]), "+f"(c[2]), "+f"(c[3])
        : "r"(a[0]), "r"(a[1]), "r"(a[2]), "r"(a[3]), "r"(b0), "r"(b1));
}

__device__ __forceinline__ void mma_fp(float* c, const uint32_t* a,
                                       uint32_t b0, uint32_t b1) {
    asm volatile(
        "mma.sync.aligned.m16n8k16.row.col.f32.f16.f16.f32 "
        "{%0,%1,%2,%3}, {%4,%5,%6,%7}, {%8,%9}, {%0,%1,%2,%3};"
        : "+f"(c[0]), "+f"(c[1]), "+f"(c[2]), "+f"(c[3])
        : "r"(a[0]), "r"(a[1]), "r"(a[2]), "r"(a[3]), "r"(b0), "r"(b1));
}

__device__ __forceinline__ void split_bf(float v, uint16_t& h, uint16_t& l) {
    __nv_bfloat16 hb = __float2bfloat16_rn(v);
    __nv_bfloat16 lb = __float2bfloat16_rn(v - __bfloat162float(hb));
    h = *(uint16_t*)&hb;
    l = *(uint16_t*)&lb;
}

// ---------------- single-fp16 HMMA GEMM (templated tile) ----------------
// C = act(A * W^T + bias)(+res); A, W single fp16.
// FM = A-fragments per warp (M per CTA = FM*32). FM=4 -> 128x128, FM=2 -> 64x128.
// FLAGS: 1=bias, 2=gelu, 4=residual(fp32), 8=write fp16, 16=write fp32,
//        64=write bf16 hi/lo pair
#define GBK   32
#define GROWB 80

template<int FLAGS, bool SPLITA, int FM, int NST>
__global__ void __launch_bounds__(256, 2) gemm_f16(
    const __half* __restrict__ Ah, const __half* __restrict__ A2h,
    const __half* __restrict__ W,
    const float* __restrict__ bias, const float* __restrict__ res,
    float* __restrict__ C, uint16_t* __restrict__ Cb,
    uint16_t* __restrict__ Cph, uint16_t* __restrict__ Cpl, int N, int K)
{
    constexpr int BM     = FM * 32;
    constexpr int ATILEB = BM * GROWB;
    constexpr int WTILEB = 128 * GROWB;
    constexpr int STRIDE = ATILEB + WTILEB;

    extern __shared__ char smem[];
    const uint32_t sb = smem_u32(smem);
    const int tid  = threadIdx.x;
    const int wid  = tid >> 5;
    const int lane = tid & 31;
    const int wm   = wid >> 2;
    const int wn   = wid & 3;
    const int bm   = blockIdx.y * BM;
    const int bn   = blockIdx.x * 128;

    // A load mapping
    const int a_r = (FM == 4) ? (tid >> 1) : (tid >> 2);
    const int a_c = (FM == 4) ? ((tid & 1) * 16) : ((tid & 3) * 8);  // halfs
    const uint32_t sA = (uint32_t)a_r * GROWB + a_c * 2;
    const size_t a_goffK = (size_t)(bm + a_r) * K + a_c;
    const size_t a_goff1 = (size_t)(bm + a_r) * 1024 + a_c;
    // W load mapping
    const int w_r = tid >> 1;
    const int w_c = (tid & 1) * 16;
    const uint32_t sW = (uint32_t)(ATILEB) + (uint32_t)w_r * GROWB + w_c * 2;
    const size_t w_goff = (size_t)(bn + w_r) * K + w_c;

    auto load_stage = [&](int s) {
        const uint32_t base = sb + (uint32_t)(s % NST) * STRIDE;
        const size_t ko = (size_t)s * GBK;
        const __half* pa;
        if (SPLITA) {
            pa = (ko >= 1024) ? (A2h + a_goff1 + (ko - 1024)) : (Ah + a_goff1 + ko);
        } else {
            pa = Ah + a_goffK + ko;
        }
        if (FM == 4) {
            cp16(base + sA,      pa);
            cp16(base + sA + 16, pa + 8);
        } else {
            cp16(base + sA, pa);
        }
        const __half* pw = W + w_goff + ko;
        cp16(base + sW,      pw);
        cp16(base + sW + 16, pw + 8);
        asm volatile("cp.async.commit_group;");
    };

    const int S = K / GBK;
    for (int s = 0; s < NST - 1; s++) load_stage(s);

    float acc[FM][4][4];
#pragma unroll
    for (int i = 0; i < FM; i++)
#pragma unroll
        for (int j = 0; j < 4; j++)
#pragma unroll
            for (int k = 0; k < 4; k++) acc[i][j][k] = 0.f;

    const uint32_t aoff = (uint32_t)(wm * (FM * 16) + (lane & 15)) * GROWB
                        + (lane >> 4) * 16;
    const uint32_t boff = (uint32_t)(wn * 32 + (lane & 7) + ((lane >> 4) & 1) * 8) * GROWB
                        + ((lane >> 3) & 1) * 16 + ATILEB;

    for (int s = 0; s < S; s++) {
        asm volatile("cp.async.wait_group %0;" :: "n"(NST - 2) : "memory");
        __syncthreads();

        const int pf = s + NST - 1;
        if (pf < S) load_stage(pf);
        else        asm volatile("cp.async.commit_group;");

        const uint32_t base = sb + (uint32_t)(s % NST) * STRIDE;
#pragma unroll
        for (int k16 = 0; k16 < 2; k16++) {
            uint32_t ah[FM][4], bb[2][4];
#pragma unroll
            for (int fm = 0; fm < FM; fm++) {
                const uint32_t ao = base + aoff + fm * 16 * GROWB + k16 * 32;
                ldm_x4(ao, ah[fm][0], ah[fm][1], ah[fm][2], ah[fm][3]);
            }
#pragma unroll
            for (int fnp = 0; fnp < 2; fnp++) {
                const uint32_t bo = base + boff + fnp * 16 * GROWB + k16 * 32;
                ldm_x4(bo, bb[fnp][0], bb[fnp][1], bb[fnp][2], bb[fnp][3]);
            }
#pragma unroll
            for (int fm = 0; fm < FM; fm++) {
#pragma unroll
                for (int fnp = 0; fnp < 2; fnp++) {
                    mma_fp(acc[fm][fnp * 2 + 0], ah[fm], bb[fnp][0], bb[fnp][1]);
                    mma_fp(acc[fm][fnp * 2 + 1], ah[fm], bb[fnp][2], bb[fnp][3]);
                }
            }
        }
    }

    // ---- epilogue ----
#pragma unroll
    for (int fm = 0; fm < FM; fm++) {
#pragma unroll
        for (int fn = 0; fn < 4; fn++) {
            const int r0 = bm + wm * (FM * 16) + fm * 16 + (lane >> 2);
            const int c0 = bn + wn * 32 + fn * 8 + (lane & 3) * 2;
            float v[4] = { acc[fm][fn][0], acc[fm][fn][1],
                           acc[fm][fn][2], acc[fm][fn][3] };
            if (FLAGS & 1) {
                const float b0 = __ldg(bias + c0), b1 = __ldg(bias + c0 + 1);
                v[0] += b0; v[1] += b1; v[2] += b0; v[3] += b1;
            }
            if (FLAGS & 2) {
#pragma unroll
                for (int u = 0; u < 4; u++)
                    v[u] = 0.5f * v[u] * (1.f + erff(v[u] * 0.7071067811865476f));
            }
            if (FLAGS & 4) {
                const float2 ra = *(const float2*)(res + (size_t)r0 * N + c0);
                const float2 rb = *(const float2*)(res + (size_t)(r0 + 8) * N + c0);
                v[0] += ra.x; v[1] += ra.y; v[2] += rb.x; v[3] += rb.y;
            }
            if (FLAGS & 16) {
                float2 oa; oa.x = v[0]; oa.y = v[1];
                float2 ob; ob.x = v[2]; ob.y = v[3];
                *(float2*)(C + (size_t)r0 * N + c0) = oa;
                *(float2*)(C + (size_t)(r0 + 8) * N + c0) = ob;
            }
            if (FLAGS & 8) {
#pragma unroll
                for (int hf = 0; hf < 2; hf++) {
                    const int rr = r0 + hf * 8;
                    __half2 p = __floats2half2_rn(v[hf * 2 + 0], v[hf * 2 + 1]);
                    *(uint32_t*)(Cb + (size_t)rr * N + c0) = *(uint32_t*)&p;
                }
            }
            if (FLAGS & 64) {
                uint16_t h0, l0, h1, l1;
#pragma unroll
                for (int hf = 0; hf < 2; hf++) {
                    const int rr = r0 + hf * 8;
                    split_bf(v[hf * 2 + 0], h0, l0);
                    split_bf(v[hf * 2 + 1], h1, l1);
                    *(uint32_t*)(Cph + (size_t)rr * N + c0) = (uint32_t)h0 | ((uint32_t)h1 << 16);
                    *(uint32_t*)(Cpl + (size_t)rr * N + c0) = (uint32_t)l0 | ((uint32_t)l1 << 16);
                }
            }
        }
    }
}

// GEMM smem sizes (single A tile + W tile, NST=4)
#define GSMEM_FM4 ((128 * GROWB + 128 * GROWB) * 4)   // 81920
#define GSMEM_FM2 ((64 * GROWB + 128 * GROWB) * 4)    // 61440

// ---------------- HMMA flash attention (bf16x3 inside, fp16 out) ------
#define ASTR 144
#define ATB  (64 * ASTR)
#define ATTN_SMEM (10 * ATB)

__global__ void __launch_bounds__(128) attn_hmma(
    const __nv_bfloat16* __restrict__ qh, const __nv_bfloat16* __restrict__ ql,
    uint16_t* __restrict__ out)
{
    extern __shared__ char smc[];
    const uint32_t sb = smem_u32(smc);
    const int b = blockIdx.z, h = blockIdx.y, q0 = blockIdx.x * 64;
    const int tid = threadIdx.x, wid = tid >> 5, lane = tid & 31;
    const float slope = -exp2f(-0.5f * (float)(h + 1));
    const size_t base = (size_t)b * 1024 * DQKV + (size_t)h * 64;

    {
        const int which = tid >> 6, r = tid & 63;
        const __nv_bfloat16* src = (which ? ql : qh) + base + (size_t)(q0 + r) * DQKV;
        const uint32_t dst = sb + which * ATB + r * ASTR;
#pragma unroll
        for (int c = 0; c < 8; c++) cp16(dst + c * 16, src + c * 8);
        asm volatile("cp.async.commit_group;");
    }

    auto load_kv = [&](int t) {
        const uint32_t bufb = sb + 2 * ATB + (t & 1) * (4 * ATB) + wid * ATB;
        const __nv_bfloat16* sp = ((wid & 1) ? ql : qh) + base + ((wid < 2) ? 1024 : 2048);
#pragma unroll
        for (int rr = 0; rr < 2; rr++) {
            const int r = lane + rr * 32;
            const __nv_bfloat16* src = sp + (size_t)(t * 64 + r) * DQKV;
            const uint32_t dst = bufb + r * ASTR;
#pragma unroll
            for (int c = 0; c < 8; c++) cp16(dst + c * 16, src + c * 8);
        }
        asm volatile("cp.async.commit_group;");
    };

    load_kv(0);
    asm volatile("cp.async.wait_group 0;" ::: "memory");
    __syncthreads();

    uint32_t qfh[4][4], qfl[4][4];
    {
        const uint32_t ao = sb + (uint32_t)(wid * 16 + (lane & 15)) * ASTR + (lane >> 4) * 16;
#pragma unroll
        for (int kk = 0; kk < 4; kk++) {
            ldm_x4(ao + kk * 32,       qfh[kk][0], qfh[kk][1], qfh[kk][2], qfh[kk][3]);
            ldm_x4(ao + ATB + kk * 32, qfl[kk][0], qfl[kk][1], qfl[kk][2], qfl[kk][3]);
        }
        const __nv_bfloat162 sc = __float2bfloat162_rn(0.125f);
#pragma unroll
        for (int kk = 0; kk < 4; kk++)
#pragma unroll
            for (int u = 0; u < 4; u++) {
                __nv_bfloat162 vh = *(__nv_bfloat162*)&qfh[kk][u];
                __nv_bfloat162 vl = *(__nv_bfloat162*)&qfl[kk][u];
                vh = __hmul2(vh, sc); vl = __hmul2(vl, sc);
                qfh[kk][u] = *(uint32_t*)&vh; qfl[kk][u] = *(uint32_t*)&vl;
            }
    }

    const int rA = q0 + wid * 16 + (lane >> 2);
    const int rB = rA + 8;
    const bool okA = rA < 1023, okB = rB < 1023;

    float m0 = -1e30f, m1 = -1e30f, l0s = 0.f, l1s = 0.f;
    float oacc[8][4];
#pragma unroll
    for (int j = 0; j < 8; j++)
#pragma unroll
        for (int u = 0; u < 4; u++) oacc[j][u] = 0.f;

    for (int t = 0; t < 16; t++) {
        if (t > 0) {
            asm volatile("cp.async.wait_group 0;" ::: "memory");
            __syncthreads();
        }
        if (t < 15) load_kv(t + 1);

        const uint32_t kb = sb + 2 * ATB + (t & 1) * (4 * ATB);
        const uint32_t vb = kb + 2 * ATB;

        float s[8][4];
#pragma unroll
        for (int j = 0; j < 8; j++)
#pragma unroll
            for (int u = 0; u < 4; u++) s[j][u] = 0.f;

        const uint32_t bbase = kb + (uint32_t)((lane & 7) + ((lane >> 4) & 1) * 8) * ASTR
                             + ((lane >> 3) & 1) * 16;
#pragma unroll
        for (int kk = 0; kk < 4; kk++) {
#pragma unroll
            for (int nb = 0; nb < 4; nb++) {
                uint32_t b0, b1, b2, b3, c0, c1, c2, c3;
                const uint32_t ad = bbase + nb * 16 * ASTR + kk * 32;
                ldm_x4(ad,       b0, b1, b2, b3);
                ldm_x4(ad + ATB, c0, c1, c2, c3);
                mma_bf(s[nb*2],   qfh[kk], b0, b1);
                mma_bf(s[nb*2],   qfl[kk], b0, b1);
                mma_bf(s[nb*2],   qfh[kk], c0, c1);
                mma_bf(s[nb*2+1], qfh[kk], b2, b3);
                mma_bf(s[nb*2+1], qfl[kk], b2, b3);
                mma_bf(s[nb*2+1], qfh[kk], c2, c3);
            }
        }

        float tmax0 = -1e30f, tmax1 = -1e30f;
#pragma unroll
        for (int j = 0; j < 8; j++) {
            const int kj = t * 64 + j * 8 + (lane & 3) * 2;
            const bool k0ok = kj < 1023, k1ok = kj + 1 < 1023;
            s[j][0] += (okA && k0ok) ? slope * fabsf((float)(rA - kj))     : 0.f;
            s[j][1] += (okA && k1ok) ? slope * fabsf((float)(rA - kj - 1)) : 0.f;
            s[j][2] += (okB && k0ok) ? slope * fabsf((float)(rB - kj))     : 0.f;
            s[j][3] += (okB && k1ok) ? slope * fabsf((float)(rB - kj - 1)) : 0.f;
            tmax0 = fmaxf(tmax0, fmaxf(s[j][0], s[j][1]));
            tmax1 = fmaxf(tmax1, fmaxf(s[j][2], s[j][3]));
        }
        tmax0 = fmaxf(tmax0, __shfl_xor_sync(0xffffffffu, tmax0, 1));
        tmax0 = fmaxf(tmax0, __shfl_xor_sync(0xffffffffu, tmax0, 2));
        tmax1 = fmaxf(tmax1, __shfl_xor_sync(0xffffffffu, tmax1, 1));
        tmax1 = fmaxf(tmax1, __shfl_xor_sync(0xffffffffu, tmax1, 2));

        const float mn0 = fmaxf(m0, tmax0), mn1 = fmaxf(m1, tmax1);
        const float al0 = __expf(m0 - mn0), al1 = __expf(m1 - mn1);
        m0 = mn0; m1 = mn1;

        float rs0 = 0.f, rs1 = 0.f;
#pragma unroll
        for (int j = 0; j < 8; j++) {
            s[j][0] = __expf(s[j][0] - mn0); rs0 += s[j][0];
            s[j][1] = __expf(s[j][1] - mn0); rs0 += s[j][1];
            s[j][2] = __expf(s[j][2] - mn1); rs1 += s[j][2];
            s[j][3] = __expf(s[j][3] - mn1); rs1 += s[j][3];
        }
        rs0 += __shfl_xor_sync(0xffffffffu, rs0, 1);
        rs0 += __shfl_xor_sync(0xffffffffu, rs0, 2);
        rs1 += __shfl_xor_sync(0xffffffffu, rs1, 1);
        rs1 += __shfl_xor_sync(0xffffffffu, rs1, 2);
        l0s = l0s * al0 + rs0;
        l1s = l1s * al1 + rs1;
#pragma unroll
        for (int j = 0; j < 8; j++) {
            oacc[j][0] *= al0; oacc[j][1] *= al0;
            oacc[j][2] *= al1; oacc[j][3] *= al1;
        }

        uint32_t pfh[4][4], pfl[4][4];
#pragma unroll
        for (int kk = 0; kk < 4; kk++) {
#pragma unroll
            for (int half = 0; half < 2; half++) {
                const int j = 2 * kk + half;
                uint16_t h0, l0, h1, l1, h2, l2, h3, l3;
                split_bf(s[j][0], h0, l0); split_bf(s[j][1], h1, l1);
                split_bf(s[j][2], h2, l2); split_bf(s[j][3], h3, l3);
                pfh[kk][half*2+0] = (uint32_t)h0 | ((uint32_t)h1 << 16);
                pfh[kk][half*2+1] = (uint32_t)h2 | ((uint32_t)h3 << 16);
                pfl[kk][half*2+0] = (uint32_t)l0 | ((uint32_t)l1 << 16);
                pfl[kk][half*2+1] = (uint32_t)l2 | ((uint32_t)l3 << 16);
            }
        }

        const uint32_t vbase = vb + (uint32_t)(((lane >> 3) & 1) * 8 + (lane & 7)) * ASTR
                             + (lane >> 4) * 16;
#pragma unroll
        for (int kk = 0; kk < 4; kk++) {
#pragma unroll
            for (int nb = 0; nb < 4; nb++) {
                uint32_t v0, v1, v2, v3, w0, w1, w2, w3;
                const uint32_t ad = vbase + kk * 16 * ASTR + nb * 32;
                ldm_x4t(ad,       v0, v1, v2, v3);
                ldm_x4t(ad + ATB, w0, w1, w2, w3);
                mma_bf(oacc[nb*2],   pfh[kk], v0, v1);
                mma_bf(oacc[nb*2],   pfl[kk], v0, v1);
                mma_bf(oacc[nb*2],   pfh[kk], w0, w1);
                mma_bf(oacc[nb*2+1], pfh[kk], v2, v3);
                mma_bf(oacc[nb*2+1], pfl[kk], v2, v3);
                mma_bf(oacc[nb*2+1], pfh[kk], w2, w3);
            }
        }
    }

    const float inv0 = 1.f / l0s, inv1 = 1.f / l1s;
#pragma unroll
    for (int j = 0; j < 8; j++) {
        const int d0 = j * 8 + (lane & 3) * 2;
        size_t o = ((size_t)b * 1024 + rA) * DMODEL + h * 64 + d0;
        __half2 pa = __floats2half2_rn(oacc[j][0] * inv0, oacc[j][1] * inv0);
        *(uint32_t*)(out + o) = *(uint32_t*)&pa;
        o += (size_t)8 * DMODEL;
        __half2 pb = __floats2half2_rn(oacc[j][2] * inv1, oacc[j][3] * inv1);
        *(uint32_t*)(out + o) = *(uint32_t*)&pb;
    }
}

// ---------------- LayerNorm ----------------
template<bool HL>
__global__ void __launch_bounds__(256) ln_kernel2(
    const float* __restrict__ x, const float* __restrict__ g,
    float* __restrict__ y, uint16_t* __restrict__ yh)
{
    __shared__ float red[256];
    const int row = blockIdx.x;
    const int tid = threadIdx.x;
    const float* xr = x + (size_t)row * DMODEL;

    float v[4];
    float s = 0.f;
#pragma unroll
    for (int u = 0; u < 4; u++) { v[u] = xr[tid + u * 256]; s += v[u]; }
    red[tid] = s; __syncthreads();
    for (int o = 128; o; o >>= 1) {
        if (tid < o) red[tid] += red[tid + o];
        __syncthreads();
    }
    const float mu = red[0] * (1.f / 1024.f);
    __syncthreads();

    float q = 0.f;
#pragma unroll
    for (int u = 0; u < 4; u++) { const float d = v[u] - mu; q += d * d; }
    red[tid] = q; __syncthreads();
    for (int o = 128; o; o >>= 1) {
        if (tid < o) red[tid] += red[tid + o];
        __syncthreads();
    }
    const float r = rsqrtf(red[0] * (1.f / 1024.f) + 1e-5f);

#pragma unroll
    for (int u = 0; u < 4; u++) {
        const float val = (v[u] - mu) * r * g[tid + u * 256];
        const size_t o = (size_t)row * DMODEL + tid + u * 256;
        if (HL) {
            __half hv = __float2half_rn(val);
            yh[o] = *(uint16_t*)&hv;
        } else {
            y[o] = val;
        }
    }
}

// ---------------- fused one-shot converter ----------------
__device__ __forceinline__ uint2 h4pack(float4 v) {
    __half2 a = __floats2half2_rn(v.x, v.y);
    __half2 b = __floats2half2_rn(v.z, v.w);
    uint2 u; u.x = *(uint32_t*)&a; u.y = *(uint32_t*)&b;
    return u;
}

__global__ void __launch_bounds__(256) convert_all(
    const float4* __restrict__ x_in, float4* __restrict__ gx,
    uint2* __restrict__ xh,
    const float4* __restrict__ qw,  uint2* __restrict__ qo,
    const float4* __restrict__ aow, uint2* __restrict__ aoo,
    const float4* __restrict__ miw, uint2* __restrict__ mio,
    const float4* __restrict__ mow, uint2* __restrict__ moo,
    const float4* __restrict__ skw, uint2* __restrict__ sko)
{
    const int stride = gridDim.x * blockDim.x;
    const int g0 = blockIdx.x * blockDim.x + threadIdx.x;

    for (int i = g0; i < TOK * DMODEL / 4; i += stride) {
        float4 v = x_in[i];
        gx[i] = v;
        xh[i] = h4pack(v);
    }
    for (int i = g0; i < NL * DQKV * DMODEL / 4; i += stride) qo[i]  = h4pack(qw[i]);
    for (int i = g0; i < NL * DMODEL * DMODEL / 4; i += stride) aoo[i] = h4pack(aow[i]);
    for (int i = g0; i < NL * DFF * DMODEL / 4; i += stride) mio[i] = h4pack(miw[i]);
    for (int i = g0; i < NL * DMODEL * DFF / 4; i += stride) moo[i] = h4pack(mow[i]);
    for (int i = g0; i < 4 * DMODEL * 2 * DMODEL / 4; i += stride) {
        float4 v = skw[i];
        if (((i * 4) & 2047) >= 1024) {
            v.x *= 0.70710678118654752440f; v.y *= 0.70710678118654752440f;
            v.z *= 0.70710678118654752440f; v.w *= 0.70710678118654752440f;
        }
        sko[i] = h4pack(v);
    }
}

// ---------------- host orchestration ----------------
extern "C" void kernel_launch(void* const* d_in, const int* in_sizes, int n_in,
                              void* d_out, int out_size)
{
    (void)in_sizes; (void)n_in; (void)out_size;
    const float* x_in       = (const float*)d_in[0];
    const float* attn_w     = (const float*)d_in[1];
    const float* attn_out_w = (const float*)d_in[2];
    const float* mlp_ln_g   = (const float*)d_in[3];
    const float* mlp_in_w   = (const float*)d_in[4];
    const float* mlp_in_b   = (const float*)d_in[5];
    const float* mlp_out_w  = (const float*)d_in[6];
    const float* mlp_out_b  = (const float*)d_in[7];
    const float* skip_w     = (const float*)d_in[8];
    const float* skip_b     = (const float*)d_in[9];
    const float* out_ln_g   = (const float*)d_in[10];

    float* gx;
    cudaGetSymbolAddress((void**)&gx, g_x);

    __half *xA, *xB, *v2, *v3, *v4, *at, *ln, *ff;
    cudaGetSymbolAddress((void**)&xA, a_xA);
    cudaGetSymbolAddress((void**)&xB, a_xB);
    cudaGetSymbolAddress((void**)&v2, s_v2);
    cudaGetSymbolAddress((void**)&v3, s_v3);
    cudaGetSymbolAddress((void**)&v4, s_v4);
    cudaGetSymbolAddress((void**)&at, a_at);
    cudaGetSymbolAddress((void**)&ln, a_ln);
    cudaGetSymbolAddress((void**)&ff, a_ff);

    __nv_bfloat16 *qkvh, *qkvl;
    cudaGetSymbolAddress((void**)&qkvh, a_qkv_h);
    cudaGetSymbolAddress((void**)&qkvl, a_qkv_l);

    __half *wq, *wao, *wmi, *wmo, *wsk;
    cudaGetSymbolAddress((void**)&wq,  w_qkv);
    cudaGetSymbolAddress((void**)&wao, w_ao);
    cudaGetSymbolAddress((void**)&wmi, w_mi);
    cudaGetSymbolAddress((void**)&wmo, w_mo);
    cudaGetSymbolAddress((void**)&wsk, w_sk);

    cudaFuncSetAttribute((const void*)gemm_f16<64, false, 2, 4>, cudaFuncAttributeMaxDynamicSharedMemorySize, GSMEM_FM2);
    cudaFuncSetAttribute((const void*)gemm_f16<28, false, 2, 4>, cudaFuncAttributeMaxDynamicSharedMemorySize, GSMEM_FM2);
    cudaFuncSetAttribute((const void*)gemm_f16<11, false, 4, 4>, cudaFuncAttributeMaxDynamicSharedMemorySize, GSMEM_FM4);
    cudaFuncSetAttribute((const void*)gemm_f16<29, false, 2, 4>, cudaFuncAttributeMaxDynamicSharedMemorySize, GSMEM_FM2);
    cudaFuncSetAttribute((const void*)gemm_f16<25, true,  2, 4>, cudaFuncAttributeMaxDynamicSharedMemorySize, GSMEM_FM2);
    cudaFuncSetAttribute(attn_hmma, cudaFuncAttributeMaxDynamicSharedMemorySize, ATTN_SMEM);

    convert_all<<<1184, 256>>>(
        (const float4*)x_in, (float4*)gx, (uint2*)xA,
        (const float4*)attn_w,     (uint2*)wq,
        (const float4*)attn_out_w, (uint2*)wao,
        (const float4*)mlp_in_w,   (uint2*)wmi,
        (const float4*)mlp_out_w,  (uint2*)wmo,
        (const float4*)skip_w,     (uint2*)wsk);

    const size_t HBYTES = sizeof(__half) * (size_t)TOK * DMODEL;

    __half* cur = xA;
    __half* alt = xB;

    for (int i = 0; i < NL; i++) {
        if (i >= 5) {
            __half* sv = (i == 5) ? v4 : (i == 6) ? v3 : v2;
            const int j = i - 4;
            gemm_f16<25, true, 2, 4><<<dim3(DMODEL / 128, TOK / 64), 256, GSMEM_FM2>>>(
                cur, sv,
                wsk + (size_t)j * DMODEL * 2 * DMODEL,
                skip_b + (size_t)j * DMODEL, nullptr,
                gx, (uint16_t*)alt, nullptr, nullptr, DMODEL, 2 * DMODEL);
            __half* t = cur; cur = alt; alt = t;
        }
        // QKV -> bf16 hi/lo (attention input)
        gemm_f16<64, false, 2, 4><<<dim3(DQKV / 128, TOK / 64), 256, GSMEM_FM2>>>(
            cur, nullptr,
            wq + (size_t)i * DQKV * DMODEL,
            nullptr, nullptr, nullptr, nullptr,
            (uint16_t*)qkvh, (uint16_t*)qkvl, DQKV, DMODEL);
        // attention (bf16x3 inside) -> fp16
        attn_hmma<<<dim3(16, 16, 2), 128, ATTN_SMEM>>>(qkvh, qkvl, (uint16_t*)at);
        // attn out proj + residual -> x (fp32 + fp16)
        gemm_f16<28, false, 2, 4><<<dim3(DMODEL / 128, TOK / 64), 256, GSMEM_FM2>>>(
            at, nullptr,
            wao + (size_t)i * DMODEL * DMODEL,
            nullptr, gx, gx, (uint16_t*)cur, nullptr, nullptr, DMODEL, DMODEL);
        // MLP LN -> fp16
        ln_kernel2<true><<<TOK, 256>>>(gx, mlp_ln_g + (size_t)i * DMODEL,
                                       nullptr, (uint16_t*)ln);
        // MLP in + bias + gelu -> fp16
        gemm_f16<11, false, 4, 4><<<dim3(DFF / 128, TOK / 128), 256, GSMEM_FM4>>>(
            ln, nullptr,
            wmi + (size_t)i * DFF * DMODEL,
            mlp_in_b + (size_t)i * DFF, nullptr, nullptr,
            (uint16_t*)ff, nullptr, nullptr, DFF, DMODEL);
        // MLP out + bias + residual -> x (fp32 + fp16)
        gemm_f16<29, false, 2, 4><<<dim3(DMODEL / 128, TOK / 64), 256, GSMEM_FM2>>>(
            ff, nullptr,
            wmo + (size_t)i * DMODEL * DFF,
            mlp_out_b + (size_t)i * DMODEL, gx, gx,
            (uint16_t*)cur, nullptr, nullptr, DMODEL, DFF);

        if (i == 2) cudaMemcpyAsync(v2, cur, HBYTES, cudaMemcpyDeviceToDevice, 0);
        if (i == 3) cudaMemcpyAsync(v3, cur, HBYTES, cudaMemcpyDeviceToDevice, 0);
        if (i == 4) cudaMemcpyAsync(v4, cur, HBYTES, cudaMemcpyDeviceToDevice, 0);
    }

    ln_kernel2<false><<<TOK, 256>>>(gx, out_ln_g, (float*)d_out, nullptr);
}